// round 7
// baseline (speedup 1.0000x reference)
#include <cuda_runtime.h>
#include <cuda_fp16.h>
#include <cstdint>
#include <math.h>

// Problem constants
#define Lc 2
#define Bc 4
#define Tc 1024
#define Dc 256
#define Hc 4
#define Mc 1024
#define NROWS (Bc*Tc)      // 4096
#define HD (Hc*Dc)         // 1024
#define LN_EPS 1e-5f

// ---------------------------------------------------------------------------
// Scratch (device globals; allocation-free contract)
// ---------------------------------------------------------------------------
__device__ float  g_x[NROWS*Dc];
__device__ float  g_proj[NROWS*Dc];
__device__ float  g_s[(long)Bc*Hc*Tc*Tc];      // fp32 attention scores (64MB)
__device__ float  g_bqkv[Lc*3*HD];             // packed QKV biases
__device__ __half g_xh[NROWS*Dc];
__device__ __half g_qkvh[3L*NROWS*HD];         // q | k | v contiguous
__device__ __half g_aoh[NROWS*HD];
__device__ __half g_hh[NROWS*Mc];
__device__ __half g_ph[(long)Bc*Hc*Tc*Tc];     // half probs (32MB)
__device__ __half g_wqkvh[Lc*3*Dc*HD];         // [l][q,k,v][D*HD]
__device__ __half g_woh[Lc*HD*Dc];
__device__ __half g_w1h[Lc*Dc*Mc];
__device__ __half g_w2h[Lc*Mc*Dc];

// ---------------------------------------------------------------------------
// Helpers
// ---------------------------------------------------------------------------
__device__ __forceinline__ uint32_t smem_u32(const void* p) {
    uint32_t a;
    asm("{ .reg .u64 t; cvta.to.shared.u64 t, %1; cvt.u32.u64 %0, t; }"
        : "=r"(a) : "l"(p));
    return a;
}
__device__ __forceinline__ void cp16(uint32_t dst, const void* src) {
    asm volatile("cp.async.cg.shared.global [%0], [%1], 16;"
                 :: "r"(dst), "l"(src) : "memory");
}
#define CP_COMMIT() asm volatile("cp.async.commit_group;" ::: "memory")
#define CP_WAIT(n)  asm volatile("cp.async.wait_group %0;" :: "n"(n) : "memory")

#define LDSM4(r, addr) \
    asm volatile("ldmatrix.sync.aligned.m8n8.x4.shared.b16 {%0,%1,%2,%3}, [%4];" \
        : "=r"((r)[0]), "=r"((r)[1]), "=r"((r)[2]), "=r"((r)[3]) : "r"(addr))
#define LDSM4T(r, addr) \
    asm volatile("ldmatrix.sync.aligned.m8n8.x4.trans.shared.b16 {%0,%1,%2,%3}, [%4];" \
        : "=r"((r)[0]), "=r"((r)[1]), "=r"((r)[2]), "=r"((r)[3]) : "r"(addr))

__device__ __forceinline__ void mma_f16(float* c, const uint32_t* a,
                                        uint32_t b0, uint32_t b1) {
    asm volatile(
        "mma.sync.aligned.m16n8k16.row.col.f32.f16.f16.f32 "
        "{%0,%1,%2,%3}, {%4,%5,%6,%7}, {%8,%9}, {%0,%1,%2,%3};"
        : "+f"(c[0]), "+f"(c[1]), "+f"(c[2]), "+f"(c[3])
        : "r"(a[0]), "r"(a[1]), "r"(a[2]), "r"(a[3]), "r"(b0), "r"(b1));
}

// ---------------------------------------------------------------------------
// Big-tile fp16 mma GEMM (2-stage cp.async). MT x 128 tile, 8 warps, BK=32.
//   TB=false: B is [N,K] K-major -> ldmatrix
//   TB=true : B is [K,N] N-major -> ldmatrix.trans
// flags bit1 = ReLU. Cf (fp32) / Ch (half) outputs, either may be null.
// Batch via blockIdx.z: z = zq*zdiv + zr; bias advances by zq*sBias.
// ---------------------------------------------------------------------------
#define BSZ 10240
template<int MT, bool TB>
__global__ void __launch_bounds__(256, 2) gemm_h(
    const __half* __restrict__ A, const __half* __restrict__ B,
    float* __restrict__ Cf, __half* __restrict__ Ch, const float* __restrict__ bias,
    int K, int lda, int ldb, int ldc,
    long sA1, long sA2, long sB1, long sB2, long sC1, long sC2, long sBias,
    int zdiv, float alpha, int flags)
{
    constexpr int ASZ = MT * 80;
    constexpr int STG = ASZ + BSZ;
    constexpr int NA  = (MT == 128) ? 2 : 1;
    constexpr int NPAIR = 4;
    constexpr int NT  = NPAIR * 2;

    extern __shared__ char smem[];
    uint32_t sbase = smem_u32(smem);

    int z  = blockIdx.z;
    int zq = z / zdiv, zr = z % zdiv;
    A  += (long)zq * sA1 + (long)zr * sA2;
    B  += (long)zq * sB1 + (long)zr * sB2;
    if (Cf)   Cf   += (long)zq * sC1 + (long)zr * sC2;
    if (Ch)   Ch   += (long)zq * sC1 + (long)zr * sC2;
    if (bias) bias += (long)zq * sBias;

    int t    = threadIdx.x;
    int lane = t & 31, w = t >> 5;
    int rowBase = blockIdx.y * MT;
    int colBase = blockIdx.x * 128;

    const __half* pA[2]; uint32_t sa[2];
    const __half* pB[2]; uint32_t sb[2];
    #pragma unroll
    for (int i = 0; i < NA; i++) {
        int idx = t + i * 256;
        int ar = idx >> 2, ac = idx & 3;
        pA[i] = A + (long)(rowBase + ar) * lda + ac * 8;
        sa[i] = (uint32_t)(ar * 80 + ac * 16);
    }
    #pragma unroll
    for (int i = 0; i < 2; i++) {
        int idx = t + i * 256;
        if (TB) {
            int kr = idx >> 4, nc = idx & 15;
            pB[i] = B + (long)kr * ldb + colBase + nc * 8;
            sb[i] = (uint32_t)(kr * 272 + nc * 16);
        } else {
            int br = idx >> 2, bc = idx & 3;
            pB[i] = B + (long)(colBase + br) * ldb + bc * 8;
            sb[i] = (uint32_t)(br * 80 + bc * 16);
        }
    }
    const long bAdv = TB ? 32L * ldb : 32L;

    int NC = K >> 5;

    {   // prologue
        uint32_t base = sbase;
        #pragma unroll
        for (int i = 0; i < NA; i++) cp16(base + sa[i], pA[i]);
        #pragma unroll
        for (int i = 0; i < 2; i++)  cp16(base + ASZ + sb[i], pB[i]);
        CP_COMMIT();
    }

    int mb = (w & 3) * 32, nb = (w >> 2) * 64;
    int g  = lane >> 3, lr = lane & 7;
    int qr = lane >> 2, cl = lane & 3;

    float acc[2][NT][4];
    #pragma unroll
    for (int i = 0; i < 2; i++)
        #pragma unroll
        for (int j = 0; j < NT; j++)
            #pragma unroll
            for (int u = 0; u < 4; u++) acc[i][j][u] = 0.0f;

    for (int c = 0; c < NC; c++) {
        int st = c & 1;
        if (c + 1 < NC) {
            uint32_t base = sbase + ((c + 1) & 1) * STG;
            #pragma unroll
            for (int i = 0; i < NA; i++) cp16(base + sa[i], pA[i] + (c + 1) * 32);
            #pragma unroll
            for (int i = 0; i < 2; i++)  cp16(base + ASZ + sb[i], pB[i] + (c + 1) * bAdv);
            CP_COMMIT();
            CP_WAIT(1);
        } else {
            CP_WAIT(0);
        }
        __syncthreads();

        uint32_t As = sbase + st * STG;
        uint32_t Bs = As + ASZ;

        #pragma unroll
        for (int kk = 0; kk < 32; kk += 16) {
            uint32_t af[2][4];
            #pragma unroll
            for (int mt = 0; mt < 2; mt++) {
                uint32_t addr = As + (uint32_t)((mb + mt * 16 + (g & 1) * 8 + lr) * 80
                                                + ((g >> 1) * 8 + kk) * 2);
                LDSM4(af[mt], addr);
            }
            #pragma unroll
            for (int np = 0; np < NPAIR; np++) {
                uint32_t bf[4];
                if (TB) {
                    uint32_t addr = Bs + (uint32_t)((kk + (g & 1) * 8 + lr) * 272
                                                    + (nb + np * 16 + (g >> 1) * 8) * 2);
                    LDSM4T(bf, addr);
                } else {
                    uint32_t addr = Bs + (uint32_t)((nb + np * 16 + (g >> 1) * 8 + lr) * 80
                                                    + ((g & 1) * 8 + kk) * 2);
                    LDSM4(bf, addr);
                }
                mma_f16(acc[0][np * 2 + 0], af[0], bf[0], bf[1]);
                mma_f16(acc[0][np * 2 + 1], af[0], bf[2], bf[3]);
                mma_f16(acc[1][np * 2 + 0], af[1], bf[0], bf[1]);
                mma_f16(acc[1][np * 2 + 1], af[1], bf[2], bf[3]);
            }
        }
        __syncthreads();
    }

    #pragma unroll
    for (int mt = 0; mt < 2; mt++) {
        int r0 = rowBase + mb + mt * 16 + qr;
        #pragma unroll
        for (int nt = 0; nt < NT; nt++) {
            int c0 = colBase + nb + nt * 8 + cl * 2;
            float b0 = 0.0f, b1 = 0.0f;
            if (bias) { b0 = bias[c0]; b1 = bias[c0 + 1]; }
            float v0 = (acc[mt][nt][0] + b0) * alpha;
            float v1 = (acc[mt][nt][1] + b1) * alpha;
            float v2 = (acc[mt][nt][2] + b0) * alpha;
            float v3 = (acc[mt][nt][3] + b1) * alpha;
            if (flags & 2) {
                v0 = fmaxf(v0, 0.0f); v1 = fmaxf(v1, 0.0f);
                v2 = fmaxf(v2, 0.0f); v3 = fmaxf(v3, 0.0f);
            }
            if (Cf) {
                *(float2*)&Cf[(long)r0 * ldc + c0]       = make_float2(v0, v1);
                *(float2*)&Cf[(long)(r0 + 8) * ldc + c0] = make_float2(v2, v3);
            }
            if (Ch) {
                *(__half2*)&Ch[(long)r0 * ldc + c0]       = __floats2half2_rn(v0, v1);
                *(__half2*)&Ch[(long)(r0 + 8) * ldc + c0] = __floats2half2_rn(v2, v3);
            }
        }
    }
}

// ---------------------------------------------------------------------------
// Small-tile fp16 mma GEMM: 64x64 tile, 4 warps (128 thr), BK=32, 2-stage.
// B is [K,N] N-major (TB=true semantics only). Static smem, high occupancy.
// ---------------------------------------------------------------------------
#define S_ASZ (64*80)        // 5120
#define S_BSZ (32*144)       // 4608
#define S_STG (S_ASZ + S_BSZ)
__global__ void __launch_bounds__(128, 4) gemm_s(
    const __half* __restrict__ A, const __half* __restrict__ B,
    float* __restrict__ Cf, __half* __restrict__ Ch, const float* __restrict__ bias,
    int K, int lda, int ldb, int ldc,
    long sA1, long sA2, long sB1, long sB2, long sC1, long sC2,
    int zdiv, float alpha, int flags)
{
    __shared__ char smem[2 * S_STG];
    uint32_t sbase = smem_u32(smem);

    int z  = blockIdx.z;
    int zq = z / zdiv, zr = z % zdiv;
    A  += (long)zq * sA1 + (long)zr * sA2;
    B  += (long)zq * sB1 + (long)zr * sB2;
    if (Cf) Cf += (long)zq * sC1 + (long)zr * sC2;
    if (Ch) Ch += (long)zq * sC1 + (long)zr * sC2;

    int t    = threadIdx.x;
    int lane = t & 31, w = t >> 5;
    int rowBase = blockIdx.y * 64;
    int colBase = blockIdx.x * 64;

    // loaders: A 64x32 half (2048 elems / 8 = 256 cp), B 32x64 (256 cp); 128 thr x2
    const __half* pA[2]; uint32_t sa[2];
    const __half* pB[2]; uint32_t sb[2];
    #pragma unroll
    for (int i = 0; i < 2; i++) {
        int idx = t + i * 128;
        int ar = idx >> 2, ac = idx & 3;
        pA[i] = A + (long)(rowBase + ar) * lda + ac * 8;
        sa[i] = (uint32_t)(ar * 80 + ac * 16);
        int kr = idx >> 3, nc = idx & 7;
        pB[i] = B + (long)kr * ldb + colBase + nc * 8;
        sb[i] = (uint32_t)(kr * 144 + nc * 16);
    }
    const long bAdv = 32L * ldb;

    int NC = K >> 5;

    {   // prologue
        #pragma unroll
        for (int i = 0; i < 2; i++) {
            cp16(sbase + sa[i], pA[i]);
            cp16(sbase + S_ASZ + sb[i], pB[i]);
        }
        CP_COMMIT();
    }

    int mb = (w & 1) * 32, nb = (w >> 1) * 32;
    int g  = lane >> 3, lr = lane & 7;
    int qr = lane >> 2, cl = lane & 3;

    float acc[2][4][4];
    #pragma unroll
    for (int i = 0; i < 2; i++)
        #pragma unroll
        for (int j = 0; j < 4; j++)
            #pragma unroll
            for (int u = 0; u < 4; u++) acc[i][j][u] = 0.0f;

    for (int c = 0; c < NC; c++) {
        int st = c & 1;
        if (c + 1 < NC) {
            uint32_t base = sbase + ((c + 1) & 1) * S_STG;
            #pragma unroll
            for (int i = 0; i < 2; i++) {
                cp16(base + sa[i], pA[i] + (c + 1) * 32);
                cp16(base + S_ASZ + sb[i], pB[i] + (c + 1) * bAdv);
            }
            CP_COMMIT();
            CP_WAIT(1);
        } else {
            CP_WAIT(0);
        }
        __syncthreads();

        uint32_t As = sbase + st * S_STG;
        uint32_t Bs = As + S_ASZ;

        #pragma unroll
        for (int kk = 0; kk < 32; kk += 16) {
            uint32_t af[2][4];
            #pragma unroll
            for (int mt = 0; mt < 2; mt++) {
                uint32_t addr = As + (uint32_t)((mb + mt * 16 + (g & 1) * 8 + lr) * 80
                                                + ((g >> 1) * 8 + kk) * 2);
                LDSM4(af[mt], addr);
            }
            #pragma unroll
            for (int np = 0; np < 2; np++) {
                uint32_t bf[4];
                uint32_t addr = Bs + (uint32_t)((kk + (g & 1) * 8 + lr) * 144
                                                + (nb + np * 16 + (g >> 1) * 8) * 2);
                LDSM4T(bf, addr);
                mma_f16(acc[0][np * 2 + 0], af[0], bf[0], bf[1]);
                mma_f16(acc[0][np * 2 + 1], af[0], bf[2], bf[3]);
                mma_f16(acc[1][np * 2 + 0], af[1], bf[0], bf[1]);
                mma_f16(acc[1][np * 2 + 1], af[1], bf[2], bf[3]);
            }
        }
        __syncthreads();
    }

    #pragma unroll
    for (int mt = 0; mt < 2; mt++) {
        int r0 = rowBase + mb + mt * 16 + qr;
        #pragma unroll
        for (int nt = 0; nt < 4; nt++) {
            int c0 = colBase + nb + nt * 8 + cl * 2;
            float b0 = 0.0f, b1 = 0.0f;
            if (bias) { b0 = bias[c0]; b1 = bias[c0 + 1]; }
            float v0 = (acc[mt][nt][0] + b0) * alpha;
            float v1 = (acc[mt][nt][1] + b1) * alpha;
            float v2 = (acc[mt][nt][2] + b0) * alpha;
            float v3 = (acc[mt][nt][3] + b1) * alpha;
            if (flags & 2) {
                v0 = fmaxf(v0, 0.0f); v1 = fmaxf(v1, 0.0f);
                v2 = fmaxf(v2, 0.0f); v3 = fmaxf(v3, 0.0f);
            }
            if (Cf) {
                *(float2*)&Cf[(long)r0 * ldc + c0]       = make_float2(v0, v1);
                *(float2*)&Cf[(long)(r0 + 8) * ldc + c0] = make_float2(v2, v3);
            }
            if (Ch) {
                *(__half2*)&Ch[(long)r0 * ldc + c0]       = __floats2half2_rn(v0, v1);
                *(__half2*)&Ch[(long)(r0 + 8) * ldc + c0] = __floats2half2_rn(v2, v3);
            }
        }
    }
}

// ---------------------------------------------------------------------------
// One-shot convert/pack kernel (see Round-6 layout).
// ---------------------------------------------------------------------------
__global__ void __launch_bounds__(256) cvt_all_k(
    const float* __restrict__ qf,
    const float* __restrict__ Wq, const float* __restrict__ Wk,
    const float* __restrict__ Wv, const float* __restrict__ Wo,
    const float* __restrict__ W1, const float* __restrict__ W2,
    const float* __restrict__ bq, const float* __restrict__ bk,
    const float* __restrict__ bv)
{
    int b = blockIdx.x;
    int tid = threadIdx.x;

    if (b >= 4096) {
        int j = b - 4096;
        int l = j / 3, tt = j % 3;
        const float* src = (tt == 0 ? bq : tt == 1 ? bk : bv) + (long)l * HD;
        float* dst = g_bqkv + (long)(l * 3 + tt) * HD;
        *(float4*)&dst[tid * 4] = *(const float4*)&src[tid * 4];
        return;
    }

    const float* src; __half* dst; long off;
    if (b < 1024) {
        src = qf; dst = g_xh; off = (long)b * 1024;
    } else if (b < 2560) {
        int i = b - 1024;
        int j = i >> 8;
        int r = i & 255;
        int l = j / 3, tt = j % 3;
        src = (tt == 0 ? Wq : tt == 1 ? Wk : Wv) + (long)l * Dc * HD;
        dst = g_wqkvh + (long)j * Dc * HD;
        off = (long)r * 1024;
    } else if (b < 3072) {
        src = Wo; dst = g_woh; off = (long)(b - 2560) * 1024;
    } else if (b < 3584) {
        src = W1; dst = g_w1h; off = (long)(b - 3072) * 1024;
    } else {
        src = W2; dst = g_w2h; off = (long)(b - 3584) * 1024;
    }
    long idx = off + tid * 4;
    float4 v = *(const float4*)&src[idx];
    *(__half2*)&dst[idx]     = __floats2half2_rn(v.x, v.y);
    *(__half2*)&dst[idx + 2] = __floats2half2_rn(v.z, v.w);
}

// ---------------------------------------------------------------------------
// Row softmax, fp32 scores -> half probs. One block (256 thr) per row (Tc).
// ---------------------------------------------------------------------------
__global__ void __launch_bounds__(256) softmax_k(const float* __restrict__ S,
                                                 __half* __restrict__ P)
{
    const float* row = S + (long)blockIdx.x * Tc;
    __half* prow = P + (long)blockIdx.x * Tc;
    int t = threadIdx.x;
    float4 v = *(const float4*)&row[t * 4];

    __shared__ float red[8];

    float m = fmaxf(fmaxf(v.x, v.y), fmaxf(v.z, v.w));
    #pragma unroll
    for (int o = 16; o > 0; o >>= 1) m = fmaxf(m, __shfl_xor_sync(0xffffffffu, m, o));
    if ((t & 31) == 0) red[t >> 5] = m;
    __syncthreads();
    m = red[0];
    #pragma unroll
    for (int w = 1; w < 8; w++) m = fmaxf(m, red[w]);

    v.x = __expf(v.x - m); v.y = __expf(v.y - m);
    v.z = __expf(v.z - m); v.w = __expf(v.w - m);
    float s = v.x + v.y + v.z + v.w;
    #pragma unroll
    for (int o = 16; o > 0; o >>= 1) s += __shfl_xor_sync(0xffffffffu, s, o);
    __syncthreads();
    if ((t & 31) == 0) red[t >> 5] = s;
    __syncthreads();
    s = 0.0f;
    #pragma unroll
    for (int w = 0; w < 8; w++) s += red[w];

    float inv = 1.0f / s;
    *(__half2*)&prow[t * 4]     = __floats2half2_rn(v.x * inv, v.y * inv);
    *(__half2*)&prow[t * 4 + 2] = __floats2half2_rn(v.z * inv, v.w * inv);
}

// ---------------------------------------------------------------------------
// Fused residual + LayerNorm, dual fp32 + fp16 output
// ---------------------------------------------------------------------------
__global__ void __launch_bounds__(256) ln_k(
    const float* __restrict__ a, const float* __restrict__ res,
    const float* __restrict__ sg, const float* __restrict__ bg,
    float* __restrict__ outF, __half* __restrict__ outH)
{
    long r = blockIdx.x;
    int  t = threadIdx.x;
    float v = a[r * Dc + t] + res[r * Dc + t];

    __shared__ float red[8];

    float s = v;
    #pragma unroll
    for (int o = 16; o > 0; o >>= 1) s += __shfl_xor_sync(0xffffffffu, s, o);
    if ((t & 31) == 0) red[t >> 5] = s;
    __syncthreads();
    s = 0.0f;
    #pragma unroll
    for (int w = 0; w < 8; w++) s += red[w];
    float mean = s * (1.0f / Dc);

    float d = v - mean;
    float q = d * d;
    #pragma unroll
    for (int o = 16; o > 0; o >>= 1) q += __shfl_xor_sync(0xffffffffu, q, o);
    __syncthreads();
    if ((t & 31) == 0) red[t >> 5] = q;
    __syncthreads();
    q = 0.0f;
    #pragma unroll
    for (int w = 0; w < 8; w++) q += red[w];
    float var = q * (1.0f / Dc);

    float o = d * rsqrtf(var + LN_EPS) * sg[t] + bg[t];
    outF[r * Dc + t] = o;
    outH[r * Dc + t] = __float2half_rn(o);
}

// ---------------------------------------------------------------------------
// Launch
// ---------------------------------------------------------------------------
extern "C" void kernel_launch(void* const* d_in, const int* in_sizes, int n_in,
                              void* d_out, int out_size)
{
    const float* queries = (const float*)d_in[0];
    const float* Wq   = (const float*)d_in[1];
    const float* bq   = (const float*)d_in[2];
    const float* Wk   = (const float*)d_in[3];
    const float* bk   = (const float*)d_in[4];
    const float* Wv   = (const float*)d_in[5];
    const float* bv   = (const float*)d_in[6];
    const float* Wo   = (const float*)d_in[7];
    const float* bo   = (const float*)d_in[8];
    const float* ln1s = (const float*)d_in[9];
    const float* ln1b = (const float*)d_in[10];
    const float* W1   = (const float*)d_in[11];
    const float* b1   = (const float*)d_in[12];
    const float* W2   = (const float*)d_in[13];
    const float* b2   = (const float*)d_in[14];
    const float* ln2s = (const float*)d_in[15];
    const float* ln2b = (const float*)d_in[16];

    float *x, *proj, *sc, *bqkv;
    __half *xh, *qkvh, *aoh, *hh, *ph;
    __half *wqkvh, *woh, *w1h, *w2h;
    cudaGetSymbolAddress((void**)&x,     g_x);
    cudaGetSymbolAddress((void**)&proj,  g_proj);
    cudaGetSymbolAddress((void**)&sc,    g_s);
    cudaGetSymbolAddress((void**)&bqkv,  g_bqkv);
    cudaGetSymbolAddress((void**)&xh,    g_xh);
    cudaGetSymbolAddress((void**)&qkvh,  g_qkvh);
    cudaGetSymbolAddress((void**)&aoh,   g_aoh);
    cudaGetSymbolAddress((void**)&hh,    g_hh);
    cudaGetSymbolAddress((void**)&ph,    g_ph);
    cudaGetSymbolAddress((void**)&wqkvh, g_wqkvh);
    cudaGetSymbolAddress((void**)&woh,   g_woh);
    cudaGetSymbolAddress((void**)&w1h,   g_w1h);
    cudaGetSymbolAddress((void**)&w2h,   g_w2h);

    const int SM128 = 2 * (128 * 80 + BSZ);  // 40960

    const float* xin = queries;
    const float qscale = 1.0f / 16.0f;

    cvt_all_k<<<4102, 256>>>(queries, Wq, Wk, Wv, Wo, W1, W2, bq, bk, bv);

    __half* qh = qkvh;
    __half* kh = qkvh + (long)NROWS * HD;
    __half* vh = qkvh + 2L * NROWS * HD;

    for (int l = 0; l < Lc; l++) {
        const __half* wqkv = wqkvh + (long)l * 3 * Dc * HD;
        const __half* wo = woh + (long)l * HD * Dc;
        const __half* w1 = w1h + (long)l * Dc * Mc;
        const __half* w2 = w2h + (long)l * Mc * Dc;
        const float* bql3 = bqkv + (long)l * 3 * HD;
        const float* bol = bo + (long)l * Dc;
        const float* b1l = b1 + (long)l * Mc;
        const float* b2l = b2 + (long)l * Dc;
        const float* s1l = ln1s + (long)l * Dc;
        const float* o1l = ln1b + (long)l * Dc;
        const float* s2l = ln2s + (long)l * Dc;
        const float* o2l = ln2b + (long)l * Dc;

        // Fused QKV (768 CTAs)
        gemm_h<128,true><<<dim3(HD/128, NROWS/128, 3), 256, SM128>>>(
            xh, wqkv, nullptr, qkvh, bql3, Dc, Dc, HD, HD,
            0, 0, (long)Dc*HD, 0, (long)NROWS*HD, 0, (long)HD,
            1, 1.0f, 0);

        // scores = (q @ k^T) * qscale  (1024 CTAs)
        gemm_h<128,false><<<dim3(Tc/128, Tc/128, Bc*Hc), 256, SM128>>>(
            qh, kh, sc, nullptr, nullptr, Dc, HD, HD, Tc,
            (long)Tc*HD, (long)Dc,
            (long)Tc*HD, (long)Dc,
            (long)Hc*Tc*Tc, (long)Tc*Tc, 0,
            Hc, qscale, 0);

        softmax_k<<<Bc*Hc*Tc, 256>>>(sc, ph);

        // PV: probs @ V  (small tiles: 4 x 16 x 16 = 1024 CTAs)
        gemm_s<<<dim3(Dc/64, Tc/64, Bc*Hc), 128>>>(
            ph, vh, nullptr, aoh, nullptr, Tc, Tc, HD, HD,
            (long)Hc*Tc*Tc, (long)Tc*Tc,
            (long)Tc*HD, (long)Dc,
            (long)Tc*HD, (long)Dc,
            Hc, 1.0f, 0);

        // Wo: [4096,1024]x[1024,256]  (4 x 64 = 256 CTAs)
        gemm_s<<<dim3(Dc/64, NROWS/64, 1), 128>>>(
            aoh, wo, proj, nullptr, bol, HD, HD, Dc, Dc,
            0,0,0,0,0,0, 1, 1.0f, 0);

        ln_k<<<NROWS, 256>>>(proj, xin, s1l, o1l, x, xh);

        // MLP1: [4096,256]x[256,1024] ReLU  (16 x 64 = 1024 CTAs)
        gemm_s<<<dim3(Mc/64, NROWS/64, 1), 128>>>(
            xh, w1, nullptr, hh, b1l, Dc, Dc, Mc, Mc,
            0,0,0,0,0,0, 1, 1.0f, 2);

        // MLP2: [4096,1024]x[1024,256]  (256 CTAs)
        gemm_s<<<dim3(Dc/64, NROWS/64, 1), 128>>>(
            hh, w2, proj, nullptr, b2l, Mc, Mc, Dc, Dc,
            0,0,0,0,0,0, 1, 1.0f, 0);

        float* lnout = (l == Lc - 1) ? (float*)d_out : x;
        ln_k<<<NROWS, 256>>>(proj, x, s2l, o2l, lnout, xh);

        xin = x;
    }
}

// round 8
// speedup vs baseline: 1.0805x; 1.0805x over previous
#include <cuda_runtime.h>
#include <cuda_fp16.h>
#include <cstdint>
#include <math.h>

// Problem constants
#define Lc 2
#define Bc 4
#define Tc 1024
#define Dc 256
#define Hc 4
#define Mc 1024
#define NROWS (Bc*Tc)      // 4096
#define HD (Hc*Dc)         // 1024
#define LN_EPS 1e-5f

// ---------------------------------------------------------------------------
// Scratch (device globals; allocation-free contract)
// ---------------------------------------------------------------------------
__device__ float  g_x[NROWS*Dc];
__device__ float  g_proj[NROWS*Dc];
__device__ float  g_s[(long)Bc*Hc*Tc*Tc];      // fp32 attention scores (64MB)
__device__ float  g_bqkv[Lc*3*HD];             // packed QKV biases
__device__ __half g_xh[NROWS*Dc];
__device__ __half g_qkvh[3L*NROWS*HD];         // q | k | v contiguous
__device__ __half g_aoh[NROWS*HD];
__device__ __half g_hh[NROWS*Mc];
__device__ __half g_ph[(long)Bc*Hc*Tc*Tc];     // half probs (32MB)
__device__ __half g_wqkvh[Lc*3*Dc*HD];         // [l][q,k,v][D*HD]
__device__ __half g_woh[Lc*HD*Dc];
__device__ __half g_w1h[Lc*Dc*Mc];
__device__ __half g_w2h[Lc*Mc*Dc];

// ---------------------------------------------------------------------------
// Helpers
// ---------------------------------------------------------------------------
__device__ __forceinline__ uint32_t smem_u32(const void* p) {
    uint32_t a;
    asm("{ .reg .u64 t; cvta.to.shared.u64 t, %1; cvt.u32.u64 %0, t; }"
        : "=r"(a) : "l"(p));
    return a;
}
__device__ __forceinline__ void cp16(uint32_t dst, const void* src) {
    asm volatile("cp.async.cg.shared.global [%0], [%1], 16;"
                 :: "r"(dst), "l"(src) : "memory");
}
#define CP_COMMIT() asm volatile("cp.async.commit_group;" ::: "memory")
#define CP_WAIT(n)  asm volatile("cp.async.wait_group %0;" :: "n"(n) : "memory")

#define LDSM4(r, addr) \
    asm volatile("ldmatrix.sync.aligned.m8n8.x4.shared.b16 {%0,%1,%2,%3}, [%4];" \
        : "=r"((r)[0]), "=r"((r)[1]), "=r"((r)[2]), "=r"((r)[3]) : "r"(addr))
#define LDSM4T(r, addr) \
    asm volatile("ldmatrix.sync.aligned.m8n8.x4.trans.shared.b16 {%0,%1,%2,%3}, [%4];" \
        : "=r"((r)[0]), "=r"((r)[1]), "=r"((r)[2]), "=r"((r)[3]) : "r"(addr))

__device__ __forceinline__ void mma_f16(float* c, const uint32_t* a,
                                        uint32_t b0, uint32_t b1) {
    asm volatile(
        "mma.sync.aligned.m16n8k16.row.col.f32.f16.f16.f32 "
        "{%0,%1,%2,%3}, {%4,%5,%6,%7}, {%8,%9}, {%0,%1,%2,%3};"
        : "+f"(c[0]), "+f"(c[1]), "+f"(c[2]), "+f"(c[3])
        : "r"(a[0]), "r"(a[1]), "r"(a[2]), "r"(a[3]), "r"(b0), "r"(b1));
}

// ---------------------------------------------------------------------------
// Big-tile fp16 mma GEMM, BK=64 (one barrier round per 64 MMAs/warp).
// 128 x 128 CTA tile, 8 warps (32x64 warp tile), 2-stage cp.async.
//   TB=false: B is [N,K] K-major -> ldmatrix
//   TB=true : B is [K,N] N-major -> ldmatrix.trans
// flags bit1 = ReLU. Cf (fp32) / Ch (half) outputs, either may be null.
// Batch via blockIdx.z: z = zq*zdiv + zr; bias advances by zq*sBias.
// SMEM: A stage 128x(64h+pad)=18432B (stride 144), B stage TB?64x272:128x144.
// ---------------------------------------------------------------------------
template<bool TB>
__global__ void __launch_bounds__(256, 2) gemm_h(
    const __half* __restrict__ A, const __half* __restrict__ B,
    float* __restrict__ Cf, __half* __restrict__ Ch, const float* __restrict__ bias,
    int K, int lda, int ldb, int ldc,
    long sA1, long sA2, long sB1, long sB2, long sC1, long sC2, long sBias,
    int zdiv, float alpha, int flags)
{
    constexpr int ASZ = 128 * 144;                    // 18432
    constexpr int BSZ2 = TB ? 64 * 272 : 128 * 144;   // 17408 / 18432
    constexpr int STG = ASZ + BSZ2;

    extern __shared__ char smem[];
    uint32_t sbase = smem_u32(smem);

    int z  = blockIdx.z;
    int zq = z / zdiv, zr = z % zdiv;
    A  += (long)zq * sA1 + (long)zr * sA2;
    B  += (long)zq * sB1 + (long)zr * sB2;
    if (Cf)   Cf   += (long)zq * sC1 + (long)zr * sC2;
    if (Ch)   Ch   += (long)zq * sC1 + (long)zr * sC2;
    if (bias) bias += (long)zq * sBias;

    int t    = threadIdx.x;
    int lane = t & 31, w = t >> 5;
    int rowBase = blockIdx.y * 128;
    int colBase = blockIdx.x * 128;

    // ---- loader bases (i-th load derived by constant offsets; 4 loads each)
    const __half* pA0 = A + (long)(rowBase + (t >> 3)) * lda + (t & 7) * 8;
    uint32_t sa0 = (uint32_t)((t >> 3) * 144 + (t & 7) * 16);
    const __half* pB0;
    uint32_t sb0;
    if (TB) {
        pB0 = B + (long)(t >> 4) * ldb + colBase + (t & 15) * 8;
        sb0 = (uint32_t)((t >> 4) * 272 + (t & 15) * 16);
    } else {
        pB0 = B + (long)(colBase + (t >> 3)) * ldb + (t & 7) * 8;
        sb0 = (uint32_t)((t >> 3) * 144 + (t & 7) * 16);
    }
    const long bChunk = TB ? 64L * ldb : 64L;          // per-chunk B advance
    const long bStepG = TB ? 16L * ldb : 32L * ldb;    // per-load-i B advance
    const uint32_t bStepS = TB ? 16u * 272 : 32u * 144;

    int NC = K >> 6;   // chunks of 64 K-elements

    {   // prologue: chunk 0 -> stage 0
        #pragma unroll
        for (int i = 0; i < 4; i++) {
            cp16(sbase + sa0 + i * (32u * 144), pA0 + (long)i * 32 * lda);
            cp16(sbase + ASZ + sb0 + i * bStepS, pB0 + (long)i * bStepG);
        }
        CP_COMMIT();
    }

    int mb = (w & 3) * 32, nb = (w >> 2) * 64;
    int g  = lane >> 3, lr = lane & 7;
    int qr = lane >> 2, cl = lane & 3;

    float acc[2][8][4];
    #pragma unroll
    for (int i = 0; i < 2; i++)
        #pragma unroll
        for (int j = 0; j < 8; j++)
            #pragma unroll
            for (int u = 0; u < 4; u++) acc[i][j][u] = 0.0f;

    for (int c = 0; c < NC; c++) {
        int st = c & 1;
        if (c + 1 < NC) {
            uint32_t base = sbase + ((c + 1) & 1) * STG;
            const __half* pAc = pA0 + (c + 1) * 64;
            const __half* pBc = pB0 + (c + 1) * bChunk;
            #pragma unroll
            for (int i = 0; i < 4; i++) {
                cp16(base + sa0 + i * (32u * 144), pAc + (long)i * 32 * lda);
                cp16(base + ASZ + sb0 + i * bStepS, pBc + (long)i * bStepG);
            }
            CP_COMMIT();
            CP_WAIT(1);
        } else {
            CP_WAIT(0);
        }
        __syncthreads();

        uint32_t As = sbase + st * STG;
        uint32_t Bs = As + ASZ;

        #pragma unroll
        for (int kk = 0; kk < 64; kk += 16) {
            uint32_t af[2][4];
            #pragma unroll
            for (int mt = 0; mt < 2; mt++) {
                uint32_t addr = As + (uint32_t)((mb + mt * 16 + (g & 1) * 8 + lr) * 144
                                                + ((g >> 1) * 8 + kk) * 2);
                LDSM4(af[mt], addr);
            }
            #pragma unroll
            for (int np = 0; np < 4; np++) {
                uint32_t bf[4];
                if (TB) {
                    uint32_t addr = Bs + (uint32_t)((kk + (g & 1) * 8 + lr) * 272
                                                    + (nb + np * 16 + (g >> 1) * 8) * 2);
                    LDSM4T(bf, addr);
                } else {
                    uint32_t addr = Bs + (uint32_t)((nb + np * 16 + (g >> 1) * 8 + lr) * 144
                                                    + ((g & 1) * 8 + kk) * 2);
                    LDSM4(bf, addr);
                }
                mma_f16(acc[0][np * 2 + 0], af[0], bf[0], bf[1]);
                mma_f16(acc[0][np * 2 + 1], af[0], bf[2], bf[3]);
                mma_f16(acc[1][np * 2 + 0], af[1], bf[0], bf[1]);
                mma_f16(acc[1][np * 2 + 1], af[1], bf[2], bf[3]);
            }
        }
        __syncthreads();
    }

    #pragma unroll
    for (int mt = 0; mt < 2; mt++) {
        int r0 = rowBase + mb + mt * 16 + qr;
        #pragma unroll
        for (int nt = 0; nt < 8; nt++) {
            int c0 = colBase + nb + nt * 8 + cl * 2;
            float b0 = 0.0f, b1 = 0.0f;
            if (bias) { b0 = bias[c0]; b1 = bias[c0 + 1]; }
            float v0 = (acc[mt][nt][0] + b0) * alpha;
            float v1 = (acc[mt][nt][1] + b1) * alpha;
            float v2 = (acc[mt][nt][2] + b0) * alpha;
            float v3 = (acc[mt][nt][3] + b1) * alpha;
            if (flags & 2) {
                v0 = fmaxf(v0, 0.0f); v1 = fmaxf(v1, 0.0f);
                v2 = fmaxf(v2, 0.0f); v3 = fmaxf(v3, 0.0f);
            }
            if (Cf) {
                *(float2*)&Cf[(long)r0 * ldc + c0]       = make_float2(v0, v1);
                *(float2*)&Cf[(long)(r0 + 8) * ldc + c0] = make_float2(v2, v3);
            }
            if (Ch) {
                *(__half2*)&Ch[(long)r0 * ldc + c0]       = __floats2half2_rn(v0, v1);
                *(__half2*)&Ch[(long)(r0 + 8) * ldc + c0] = __floats2half2_rn(v2, v3);
            }
        }
    }
}

// ---------------------------------------------------------------------------
// Small-tile fp16 mma GEMM: 64x64 tile, 4 warps, BK=32, 2-stage, static smem.
// B is [K,N] N-major (trans). Used for Wo / MLP1 / MLP2.
// ---------------------------------------------------------------------------
#define S_ASZ (64*80)
#define S_BSZ (32*144)
#define S_STG (S_ASZ + S_BSZ)
__global__ void __launch_bounds__(128, 4) gemm_s(
    const __half* __restrict__ A, const __half* __restrict__ B,
    float* __restrict__ Cf, __half* __restrict__ Ch, const float* __restrict__ bias,
    int K, int lda, int ldb, int ldc,
    long sA1, long sA2, long sB1, long sB2, long sC1, long sC2,
    int zdiv, float alpha, int flags)
{
    __shared__ char smem[2 * S_STG];
    uint32_t sbase = smem_u32(smem);

    int z  = blockIdx.z;
    int zq = z / zdiv, zr = z % zdiv;
    A  += (long)zq * sA1 + (long)zr * sA2;
    B  += (long)zq * sB1 + (long)zr * sB2;
    if (Cf) Cf += (long)zq * sC1 + (long)zr * sC2;
    if (Ch) Ch += (long)zq * sC1 + (long)zr * sC2;

    int t    = threadIdx.x;
    int lane = t & 31, w = t >> 5;
    int rowBase = blockIdx.y * 64;
    int colBase = blockIdx.x * 64;

    const __half* pA[2]; uint32_t sa[2];
    const __half* pB[2]; uint32_t sb[2];
    #pragma unroll
    for (int i = 0; i < 2; i++) {
        int idx = t + i * 128;
        int ar = idx >> 2, ac = idx & 3;
        pA[i] = A + (long)(rowBase + ar) * lda + ac * 8;
        sa[i] = (uint32_t)(ar * 80 + ac * 16);
        int kr = idx >> 3, nc = idx & 7;
        pB[i] = B + (long)kr * ldb + colBase + nc * 8;
        sb[i] = (uint32_t)(kr * 144 + nc * 16);
    }
    const long bAdv = 32L * ldb;

    int NC = K >> 5;

    {
        #pragma unroll
        for (int i = 0; i < 2; i++) {
            cp16(sbase + sa[i], pA[i]);
            cp16(sbase + S_ASZ + sb[i], pB[i]);
        }
        CP_COMMIT();
    }

    int mb = (w & 1) * 32, nb = (w >> 1) * 32;
    int g  = lane >> 3, lr = lane & 7;
    int qr = lane >> 2, cl = lane & 3;

    float acc[2][4][4];
    #pragma unroll
    for (int i = 0; i < 2; i++)
        #pragma unroll
        for (int j = 0; j < 4; j++)
            #pragma unroll
            for (int u = 0; u < 4; u++) acc[i][j][u] = 0.0f;

    for (int c = 0; c < NC; c++) {
        int st = c & 1;
        if (c + 1 < NC) {
            uint32_t base = sbase + ((c + 1) & 1) * S_STG;
            #pragma unroll
            for (int i = 0; i < 2; i++) {
                cp16(base + sa[i], pA[i] + (c + 1) * 32);
                cp16(base + S_ASZ + sb[i], pB[i] + (c + 1) * bAdv);
            }
            CP_COMMIT();
            CP_WAIT(1);
        } else {
            CP_WAIT(0);
        }
        __syncthreads();

        uint32_t As = sbase + st * S_STG;
        uint32_t Bs = As + S_ASZ;

        #pragma unroll
        for (int kk = 0; kk < 32; kk += 16) {
            uint32_t af[2][4];
            #pragma unroll
            for (int mt = 0; mt < 2; mt++) {
                uint32_t addr = As + (uint32_t)((mb + mt * 16 + (g & 1) * 8 + lr) * 80
                                                + ((g >> 1) * 8 + kk) * 2);
                LDSM4(af[mt], addr);
            }
            #pragma unroll
            for (int np = 0; np < 2; np++) {
                uint32_t bf[4];
                uint32_t addr = Bs + (uint32_t)((kk + (g & 1) * 8 + lr) * 144
                                                + (nb + np * 16 + (g >> 1) * 8) * 2);
                LDSM4T(bf, addr);
                mma_f16(acc[0][np * 2 + 0], af[0], bf[0], bf[1]);
                mma_f16(acc[0][np * 2 + 1], af[0], bf[2], bf[3]);
                mma_f16(acc[1][np * 2 + 0], af[1], bf[0], bf[1]);
                mma_f16(acc[1][np * 2 + 1], af[1], bf[2], bf[3]);
            }
        }
        __syncthreads();
    }

    #pragma unroll
    for (int mt = 0; mt < 2; mt++) {
        int r0 = rowBase + mb + mt * 16 + qr;
        #pragma unroll
        for (int nt = 0; nt < 4; nt++) {
            int c0 = colBase + nb + nt * 8 + cl * 2;
            float b0 = 0.0f, b1 = 0.0f;
            if (bias) { b0 = bias[c0]; b1 = bias[c0 + 1]; }
            float v0 = (acc[mt][nt][0] + b0) * alpha;
            float v1 = (acc[mt][nt][1] + b1) * alpha;
            float v2 = (acc[mt][nt][2] + b0) * alpha;
            float v3 = (acc[mt][nt][3] + b1) * alpha;
            if (flags & 2) {
                v0 = fmaxf(v0, 0.0f); v1 = fmaxf(v1, 0.0f);
                v2 = fmaxf(v2, 0.0f); v3 = fmaxf(v3, 0.0f);
            }
            if (Cf) {
                *(float2*)&Cf[(long)r0 * ldc + c0]       = make_float2(v0, v1);
                *(float2*)&Cf[(long)(r0 + 8) * ldc + c0] = make_float2(v2, v3);
            }
            if (Ch) {
                *(__half2*)&Ch[(long)r0 * ldc + c0]       = __floats2half2_rn(v0, v1);
                *(__half2*)&Ch[(long)(r0 + 8) * ldc + c0] = __floats2half2_rn(v2, v3);
            }
        }
    }
}

// ---------------------------------------------------------------------------
// One-shot convert/pack kernel (see Round-6 layout).
// ---------------------------------------------------------------------------
__global__ void __launch_bounds__(256) cvt_all_k(
    const float* __restrict__ qf,
    const float* __restrict__ Wq, const float* __restrict__ Wk,
    const float* __restrict__ Wv, const float* __restrict__ Wo,
    const float* __restrict__ W1, const float* __restrict__ W2,
    const float* __restrict__ bq, const float* __restrict__ bk,
    const float* __restrict__ bv)
{
    int b = blockIdx.x;
    int tid = threadIdx.x;

    if (b >= 4096) {
        int j = b - 4096;
        int l = j / 3, tt = j % 3;
        const float* src = (tt == 0 ? bq : tt == 1 ? bk : bv) + (long)l * HD;
        float* dst = g_bqkv + (long)(l * 3 + tt) * HD;
        *(float4*)&dst[tid * 4] = *(const float4*)&src[tid * 4];
        return;
    }

    const float* src; __half* dst; long off;
    if (b < 1024) {
        src = qf; dst = g_xh; off = (long)b * 1024;
    } else if (b < 2560) {
        int i = b - 1024;
        int j = i >> 8;
        int r = i & 255;
        int l = j / 3, tt = j % 3;
        src = (tt == 0 ? Wq : tt == 1 ? Wk : Wv) + (long)l * Dc * HD;
        dst = g_wqkvh + (long)j * Dc * HD;
        off = (long)r * 1024;
    } else if (b < 3072) {
        src = Wo; dst = g_woh; off = (long)(b - 2560) * 1024;
    } else if (b < 3584) {
        src = W1; dst = g_w1h; off = (long)(b - 3072) * 1024;
    } else {
        src = W2; dst = g_w2h; off = (long)(b - 3584) * 1024;
    }
    long idx = off + tid * 4;
    float4 v = *(const float4*)&src[idx];
    *(__half2*)&dst[idx]     = __floats2half2_rn(v.x, v.y);
    *(__half2*)&dst[idx + 2] = __floats2half2_rn(v.z, v.w);
}

// ---------------------------------------------------------------------------
// Row softmax, fp32 scores -> half probs. One block (256 thr) per row (Tc).
// ---------------------------------------------------------------------------
__global__ void __launch_bounds__(256) softmax_k(const float* __restrict__ S,
                                                 __half* __restrict__ P)
{
    const float* row = S + (long)blockIdx.x * Tc;
    __half* prow = P + (long)blockIdx.x * Tc;
    int t = threadIdx.x;
    float4 v = *(const float4*)&row[t * 4];

    __shared__ float red[8];

    float m = fmaxf(fmaxf(v.x, v.y), fmaxf(v.z, v.w));
    #pragma unroll
    for (int o = 16; o > 0; o >>= 1) m = fmaxf(m, __shfl_xor_sync(0xffffffffu, m, o));
    if ((t & 31) == 0) red[t >> 5] = m;
    __syncthreads();
    m = red[0];
    #pragma unroll
    for (int w = 1; w < 8; w++) m = fmaxf(m, red[w]);

    v.x = __expf(v.x - m); v.y = __expf(v.y - m);
    v.z = __expf(v.z - m); v.w = __expf(v.w - m);
    float s = v.x + v.y + v.z + v.w;
    #pragma unroll
    for (int o = 16; o > 0; o >>= 1) s += __shfl_xor_sync(0xffffffffu, s, o);
    __syncthreads();
    if ((t & 31) == 0) red[t >> 5] = s;
    __syncthreads();
    s = 0.0f;
    #pragma unroll
    for (int w = 0; w < 8; w++) s += red[w];

    float inv = 1.0f / s;
    *(__half2*)&prow[t * 4]     = __floats2half2_rn(v.x * inv, v.y * inv);
    *(__half2*)&prow[t * 4 + 2] = __floats2half2_rn(v.z * inv, v.w * inv);
}

// ---------------------------------------------------------------------------
// Fused residual + LayerNorm, dual fp32 + fp16 output
// ---------------------------------------------------------------------------
__global__ void __launch_bounds__(256) ln_k(
    const float* __restrict__ a, const float* __restrict__ res,
    const float* __restrict__ sg, const float* __restrict__ bg,
    float* __restrict__ outF, __half* __restrict__ outH)
{
    long r = blockIdx.x;
    int  t = threadIdx.x;
    float v = a[r * Dc + t] + res[r * Dc + t];

    __shared__ float red[8];

    float s = v;
    #pragma unroll
    for (int o = 16; o > 0; o >>= 1) s += __shfl_xor_sync(0xffffffffu, s, o);
    if ((t & 31) == 0) red[t >> 5] = s;
    __syncthreads();
    s = 0.0f;
    #pragma unroll
    for (int w = 0; w < 8; w++) s += red[w];
    float mean = s * (1.0f / Dc);

    float d = v - mean;
    float q = d * d;
    #pragma unroll
    for (int o = 16; o > 0; o >>= 1) q += __shfl_xor_sync(0xffffffffu, q, o);
    __syncthreads();
    if ((t & 31) == 0) red[t >> 5] = q;
    __syncthreads();
    q = 0.0f;
    #pragma unroll
    for (int w = 0; w < 8; w++) q += red[w];
    float var = q * (1.0f / Dc);

    float o = d * rsqrtf(var + LN_EPS) * sg[t] + bg[t];
    outF[r * Dc + t] = o;
    outH[r * Dc + t] = __float2half_rn(o);
}

// ---------------------------------------------------------------------------
// Launch
// ---------------------------------------------------------------------------
extern "C" void kernel_launch(void* const* d_in, const int* in_sizes, int n_in,
                              void* d_out, int out_size)
{
    const float* queries = (const float*)d_in[0];
    const float* Wq   = (const float*)d_in[1];
    const float* bq   = (const float*)d_in[2];
    const float* Wk   = (const float*)d_in[3];
    const float* bk   = (const float*)d_in[4];
    const float* Wv   = (const float*)d_in[5];
    const float* bv   = (const float*)d_in[6];
    const float* Wo   = (const float*)d_in[7];
    const float* bo   = (const float*)d_in[8];
    const float* ln1s = (const float*)d_in[9];
    const float* ln1b = (const float*)d_in[10];
    const float* W1   = (const float*)d_in[11];
    const float* b1   = (const float*)d_in[12];
    const float* W2   = (const float*)d_in[13];
    const float* b2   = (const float*)d_in[14];
    const float* ln2s = (const float*)d_in[15];
    const float* ln2b = (const float*)d_in[16];

    float *x, *proj, *sc, *bqkv;
    __half *xh, *qkvh, *aoh, *hh, *ph;
    __half *wqkvh, *woh, *w1h, *w2h;
    cudaGetSymbolAddress((void**)&x,     g_x);
    cudaGetSymbolAddress((void**)&proj,  g_proj);
    cudaGetSymbolAddress((void**)&sc,    g_s);
    cudaGetSymbolAddress((void**)&bqkv,  g_bqkv);
    cudaGetSymbolAddress((void**)&xh,    g_xh);
    cudaGetSymbolAddress((void**)&qkvh,  g_qkvh);
    cudaGetSymbolAddress((void**)&aoh,   g_aoh);
    cudaGetSymbolAddress((void**)&hh,    g_hh);
    cudaGetSymbolAddress((void**)&ph,    g_ph);
    cudaGetSymbolAddress((void**)&wqkvh, g_wqkvh);
    cudaGetSymbolAddress((void**)&woh,   g_woh);
    cudaGetSymbolAddress((void**)&w1h,   g_w1h);
    cudaGetSymbolAddress((void**)&w2h,   g_w2h);

    const int SMH_T = 2 * (128*144 + 64*272);   // 71680
    const int SMH_F = 2 * (128*144 + 128*144);  // 73728
    cudaFuncSetAttribute(gemm_h<true>,  cudaFuncAttributeMaxDynamicSharedMemorySize, SMH_T);
    cudaFuncSetAttribute(gemm_h<false>, cudaFuncAttributeMaxDynamicSharedMemorySize, SMH_F);

    const float* xin = queries;
    const float qscale = 1.0f / 16.0f;

    cvt_all_k<<<4102, 256>>>(queries, Wq, Wk, Wv, Wo, W1, W2, bq, bk, bv);

    __half* qh = qkvh;
    __half* kh = qkvh + (long)NROWS * HD;
    __half* vh = qkvh + 2L * NROWS * HD;

    for (int l = 0; l < Lc; l++) {
        const __half* wqkv = wqkvh + (long)l * 3 * Dc * HD;
        const __half* wo = woh + (long)l * HD * Dc;
        const __half* w1 = w1h + (long)l * Dc * Mc;
        const __half* w2 = w2h + (long)l * Mc * Dc;
        const float* bql3 = bqkv + (long)l * 3 * HD;
        const float* bol = bo + (long)l * Dc;
        const float* b1l = b1 + (long)l * Mc;
        const float* b2l = b2 + (long)l * Dc;
        const float* s1l = ln1s + (long)l * Dc;
        const float* o1l = ln1b + (long)l * Dc;
        const float* s2l = ln2s + (long)l * Dc;
        const float* o2l = ln2b + (long)l * Dc;

        // Fused QKV (768 CTAs, K=256 -> 4 chunks)
        gemm_h<true><<<dim3(HD/128, NROWS/128, 3), 256, SMH_T>>>(
            xh, wqkv, nullptr, qkvh, bql3, Dc, Dc, HD, HD,
            0, 0, (long)Dc*HD, 0, (long)NROWS*HD, 0, (long)HD,
            1, 1.0f, 0);

        // scores = (q @ k^T) * qscale  (1024 CTAs, K=256)
        gemm_h<false><<<dim3(Tc/128, Tc/128, Bc*Hc), 256, SMH_F>>>(
            qh, kh, sc, nullptr, nullptr, Dc, HD, HD, Tc,
            (long)Tc*HD, (long)Dc,
            (long)Tc*HD, (long)Dc,
            (long)Hc*Tc*Tc, (long)Tc*Tc, 0,
            Hc, qscale, 0);

        softmax_k<<<Bc*Hc*Tc, 256>>>(sc, ph);

        // PV: probs @ V  (256 CTAs, K=1024 -> 16 chunks)
        gemm_h<true><<<dim3(Dc/128, Tc/128, Bc*Hc), 256, SMH_T>>>(
            ph, vh, nullptr, aoh, nullptr, Tc, Tc, HD, HD,
            (long)Hc*Tc*Tc, (long)Tc*Tc,
            (long)Tc*HD, (long)Dc,
            (long)Tc*HD, (long)Dc, 0,
            Hc, 1.0f, 0);

        // Wo: [4096,1024]x[1024,256]
        gemm_s<<<dim3(Dc/64, NROWS/64, 1), 128>>>(
            aoh, wo, proj, nullptr, bol, HD, HD, Dc, Dc,
            0,0,0,0,0,0, 1, 1.0f, 0);

        ln_k<<<NROWS, 256>>>(proj, xin, s1l, o1l, x, xh);

        // MLP1: [4096,256]x[256,1024] ReLU
        gemm_s<<<dim3(Mc/64, NROWS/64, 1), 128>>>(
            xh, w1, nullptr, hh, b1l, Dc, Dc, Mc, Mc,
            0,0,0,0,0,0, 1, 1.0f, 2);

        // MLP2: [4096,1024]x[1024,256]
        gemm_s<<<dim3(Dc/64, NROWS/64, 1), 128>>>(
            hh, w2, proj, nullptr, b2l, Mc, Mc, Dc, Dc,
            0,0,0,0,0,0, 1, 1.0f, 0);

        float* lnout = (l == Lc - 1) ? (float*)d_out : x;
        ln_k<<<NROWS, 256>>>(proj, x, s2l, o2l, lnout, xh);

        xin = x;
    }
}

// round 9
// speedup vs baseline: 1.1495x; 1.0638x over previous
#include <cuda_runtime.h>
#include <cuda_fp16.h>
#include <cstdint>
#include <math.h>

// Problem constants
#define Lc 2
#define Bc 4
#define Tc 1024
#define Dc 256
#define Hc 4
#define Mc 1024
#define NROWS (Bc*Tc)      // 4096
#define HD (Hc*Dc)         // 1024
#define LN_EPS 1e-5f

// ---------------------------------------------------------------------------
// Scratch (device globals; allocation-free contract)
// ---------------------------------------------------------------------------
__device__ float  g_x[NROWS*Dc];
__device__ float  g_part[4L*NROWS*Dc];         // split-K partials (16MB)
__device__ float  g_s[(long)Bc*Hc*Tc*Tc];      // fp32 attention scores (64MB)
__device__ float  g_bqkv[Lc*3*HD];             // packed QKV biases
__device__ __half g_xh[NROWS*Dc];
__device__ __half g_qkvh[3L*NROWS*HD];         // q | k | v contiguous
__device__ __half g_aoh[NROWS*HD];
__device__ __half g_hh[NROWS*Mc];
__device__ __half g_ph[(long)Bc*Hc*Tc*Tc];     // half probs (32MB)
__device__ __half g_wqkvh[Lc*3*Dc*HD];         // [l][q,k,v][D*HD]
__device__ __half g_woh[Lc*HD*Dc];
__device__ __half g_w1h[Lc*Dc*Mc];
__device__ __half g_w2h[Lc*Mc*Dc];

// ---------------------------------------------------------------------------
// Helpers
// ---------------------------------------------------------------------------
__device__ __forceinline__ uint32_t smem_u32(const void* p) {
    uint32_t a;
    asm("{ .reg .u64 t; cvta.to.shared.u64 t, %1; cvt.u32.u64 %0, t; }"
        : "=r"(a) : "l"(p));
    return a;
}
__device__ __forceinline__ void cp16(uint32_t dst, const void* src) {
    asm volatile("cp.async.cg.shared.global [%0], [%1], 16;"
                 :: "r"(dst), "l"(src) : "memory");
}
#define CP_COMMIT() asm volatile("cp.async.commit_group;" ::: "memory")
#define CP_WAIT(n)  asm volatile("cp.async.wait_group %0;" :: "n"(n) : "memory")

#define LDSM4(r, addr) \
    asm volatile("ldmatrix.sync.aligned.m8n8.x4.shared.b16 {%0,%1,%2,%3}, [%4];" \
        : "=r"((r)[0]), "=r"((r)[1]), "=r"((r)[2]), "=r"((r)[3]) : "r"(addr))
#define LDSM4T(r, addr) \
    asm volatile("ldmatrix.sync.aligned.m8n8.x4.trans.shared.b16 {%0,%1,%2,%3}, [%4];" \
        : "=r"((r)[0]), "=r"((r)[1]), "=r"((r)[2]), "=r"((r)[3]) : "r"(addr))

__device__ __forceinline__ void mma_f16(float* c, const uint32_t* a,
                                        uint32_t b0, uint32_t b1) {
    asm volatile(
        "mma.sync.aligned.m16n8k16.row.col.f32.f16.f16.f32 "
        "{%0,%1,%2,%3}, {%4,%5,%6,%7}, {%8,%9}, {%0,%1,%2,%3};"
        : "+f"(c[0]), "+f"(c[1]), "+f"(c[2]), "+f"(c[3])
        : "r"(a[0]), "r"(a[1]), "r"(a[2]), "r"(a[3]), "r"(b0), "r"(b1));
}

// ---------------------------------------------------------------------------
// Big-tile fp16 mma GEMM, BK=64. 128x128 CTA tile, 8 warps, 2-stage cp.async.
//   TB=false: B is [N,K] K-major -> ldmatrix
//   TB=true : B is [K,N] N-major -> ldmatrix.trans
// flags bit1 = ReLU. Cf (fp32) / Ch (half), either may be null.
// blockIdx.z: z = zq*zdiv + zr; offsets via per-operand strides; split-K is
// expressed by advancing A/B along K per z and writing partial slabs via sC1.
// ---------------------------------------------------------------------------
template<bool TB>
__global__ void __launch_bounds__(256, 2) gemm_h(
    const __half* __restrict__ A, const __half* __restrict__ B,
    float* __restrict__ Cf, __half* __restrict__ Ch, const float* __restrict__ bias,
    int K, int lda, int ldb, int ldc,
    long sA1, long sA2, long sB1, long sB2, long sC1, long sC2, long sBias,
    int zdiv, float alpha, int flags)
{
    constexpr int ASZ = 128 * 144;                    // 18432
    constexpr int BSZ2 = TB ? 64 * 272 : 128 * 144;
    constexpr int STG = ASZ + BSZ2;

    extern __shared__ char smem[];
    uint32_t sbase = smem_u32(smem);

    int z  = blockIdx.z;
    int zq = z / zdiv, zr = z % zdiv;
    A  += (long)zq * sA1 + (long)zr * sA2;
    B  += (long)zq * sB1 + (long)zr * sB2;
    if (Cf)   Cf   += (long)zq * sC1 + (long)zr * sC2;
    if (Ch)   Ch   += (long)zq * sC1 + (long)zr * sC2;
    if (bias) bias += (long)zq * sBias;

    int t    = threadIdx.x;
    int lane = t & 31, w = t >> 5;
    int rowBase = blockIdx.y * 128;
    int colBase = blockIdx.x * 128;

    const __half* pA0 = A + (long)(rowBase + (t >> 3)) * lda + (t & 7) * 8;
    uint32_t sa0 = (uint32_t)((t >> 3) * 144 + (t & 7) * 16);
    const __half* pB0;
    uint32_t sb0;
    if (TB) {
        pB0 = B + (long)(t >> 4) * ldb + colBase + (t & 15) * 8;
        sb0 = (uint32_t)((t >> 4) * 272 + (t & 15) * 16);
    } else {
        pB0 = B + (long)(colBase + (t >> 3)) * ldb + (t & 7) * 8;
        sb0 = (uint32_t)((t >> 3) * 144 + (t & 7) * 16);
    }
    const long bChunk = TB ? 64L * ldb : 64L;
    const long bStepG = TB ? 16L * ldb : 32L * ldb;
    const uint32_t bStepS = TB ? 16u * 272 : 32u * 144;

    int NC = K >> 6;

    {   // prologue
        #pragma unroll
        for (int i = 0; i < 4; i++) {
            cp16(sbase + sa0 + i * (32u * 144), pA0 + (long)i * 32 * lda);
            cp16(sbase + ASZ + sb0 + i * bStepS, pB0 + (long)i * bStepG);
        }
        CP_COMMIT();
    }

    int mb = (w & 3) * 32, nb = (w >> 2) * 64;
    int g  = lane >> 3, lr = lane & 7;
    int qr = lane >> 2, cl = lane & 3;

    float acc[2][8][4];
    #pragma unroll
    for (int i = 0; i < 2; i++)
        #pragma unroll
        for (int j = 0; j < 8; j++)
            #pragma unroll
            for (int u = 0; u < 4; u++) acc[i][j][u] = 0.0f;

    for (int c = 0; c < NC; c++) {
        int st = c & 1;
        if (c + 1 < NC) {
            uint32_t base = sbase + ((c + 1) & 1) * STG;
            const __half* pAc = pA0 + (c + 1) * 64;
            const __half* pBc = pB0 + (c + 1) * bChunk;
            #pragma unroll
            for (int i = 0; i < 4; i++) {
                cp16(base + sa0 + i * (32u * 144), pAc + (long)i * 32 * lda);
                cp16(base + ASZ + sb0 + i * bStepS, pBc + (long)i * bStepG);
            }
            CP_COMMIT();
            CP_WAIT(1);
        } else {
            CP_WAIT(0);
        }
        __syncthreads();

        uint32_t As = sbase + st * STG;
        uint32_t Bs = As + ASZ;

        #pragma unroll
        for (int kk = 0; kk < 64; kk += 16) {
            uint32_t af[2][4];
            #pragma unroll
            for (int mt = 0; mt < 2; mt++) {
                uint32_t addr = As + (uint32_t)((mb + mt * 16 + (g & 1) * 8 + lr) * 144
                                                + ((g >> 1) * 8 + kk) * 2);
                LDSM4(af[mt], addr);
            }
            #pragma unroll
            for (int np = 0; np < 4; np++) {
                uint32_t bf[4];
                if (TB) {
                    uint32_t addr = Bs + (uint32_t)((kk + (g & 1) * 8 + lr) * 272
                                                    + (nb + np * 16 + (g >> 1) * 8) * 2);
                    LDSM4T(bf, addr);
                } else {
                    uint32_t addr = Bs + (uint32_t)((nb + np * 16 + (g >> 1) * 8 + lr) * 144
                                                    + ((g & 1) * 8 + kk) * 2);
                    LDSM4(bf, addr);
                }
                mma_f16(acc[0][np * 2 + 0], af[0], bf[0], bf[1]);
                mma_f16(acc[0][np * 2 + 1], af[0], bf[2], bf[3]);
                mma_f16(acc[1][np * 2 + 0], af[1], bf[0], bf[1]);
                mma_f16(acc[1][np * 2 + 1], af[1], bf[2], bf[3]);
            }
        }
        __syncthreads();
    }

    #pragma unroll
    for (int mt = 0; mt < 2; mt++) {
        int r0 = rowBase + mb + mt * 16 + qr;
        #pragma unroll
        for (int nt = 0; nt < 8; nt++) {
            int c0 = colBase + nb + nt * 8 + cl * 2;
            float b0 = 0.0f, b1 = 0.0f;
            if (bias) { b0 = bias[c0]; b1 = bias[c0 + 1]; }
            float v0 = (acc[mt][nt][0] + b0) * alpha;
            float v1 = (acc[mt][nt][1] + b1) * alpha;
            float v2 = (acc[mt][nt][2] + b0) * alpha;
            float v3 = (acc[mt][nt][3] + b1) * alpha;
            if (flags & 2) {
                v0 = fmaxf(v0, 0.0f); v1 = fmaxf(v1, 0.0f);
                v2 = fmaxf(v2, 0.0f); v3 = fmaxf(v3, 0.0f);
            }
            if (Cf) {
                *(float2*)&Cf[(long)r0 * ldc + c0]       = make_float2(v0, v1);
                *(float2*)&Cf[(long)(r0 + 8) * ldc + c0] = make_float2(v2, v3);
            }
            if (Ch) {
                *(__half2*)&Ch[(long)r0 * ldc + c0]       = __floats2half2_rn(v0, v1);
                *(__half2*)&Ch[(long)(r0 + 8) * ldc + c0] = __floats2half2_rn(v2, v3);
            }
        }
    }
}

// ---------------------------------------------------------------------------
// One-shot convert/pack kernel (Round-6 layout).
// ---------------------------------------------------------------------------
__global__ void __launch_bounds__(256) cvt_all_k(
    const float* __restrict__ qf,
    const float* __restrict__ Wq, const float* __restrict__ Wk,
    const float* __restrict__ Wv, const float* __restrict__ Wo,
    const float* __restrict__ W1, const float* __restrict__ W2,
    const float* __restrict__ bq, const float* __restrict__ bk,
    const float* __restrict__ bv)
{
    int b = blockIdx.x;
    int tid = threadIdx.x;

    if (b >= 4096) {
        int j = b - 4096;
        int l = j / 3, tt = j % 3;
        const float* src = (tt == 0 ? bq : tt == 1 ? bk : bv) + (long)l * HD;
        float* dst = g_bqkv + (long)(l * 3 + tt) * HD;
        *(float4*)&dst[tid * 4] = *(const float4*)&src[tid * 4];
        return;
    }

    const float* src; __half* dst; long off;
    if (b < 1024) {
        src = qf; dst = g_xh; off = (long)b * 1024;
    } else if (b < 2560) {
        int i = b - 1024;
        int j = i >> 8;
        int r = i & 255;
        int l = j / 3, tt = j % 3;
        src = (tt == 0 ? Wq : tt == 1 ? Wk : Wv) + (long)l * Dc * HD;
        dst = g_wqkvh + (long)j * Dc * HD;
        off = (long)r * 1024;
    } else if (b < 3072) {
        src = Wo; dst = g_woh; off = (long)(b - 2560) * 1024;
    } else if (b < 3584) {
        src = W1; dst = g_w1h; off = (long)(b - 3072) * 1024;
    } else {
        src = W2; dst = g_w2h; off = (long)(b - 3584) * 1024;
    }
    long idx = off + tid * 4;
    float4 v = *(const float4*)&src[idx];
    *(__half2*)&dst[idx]     = __floats2half2_rn(v.x, v.y);
    *(__half2*)&dst[idx + 2] = __floats2half2_rn(v.z, v.w);
}

// ---------------------------------------------------------------------------
// Row softmax, fp32 scores -> half probs. One block (256 thr) per row (Tc).
// ---------------------------------------------------------------------------
__global__ void __launch_bounds__(256) softmax_k(const float* __restrict__ S,
                                                 __half* __restrict__ P)
{
    const float* row = S + (long)blockIdx.x * Tc;
    __half* prow = P + (long)blockIdx.x * Tc;
    int t = threadIdx.x;
    float4 v = *(const float4*)&row[t * 4];

    __shared__ float red[8];

    float m = fmaxf(fmaxf(v.x, v.y), fmaxf(v.z, v.w));
    #pragma unroll
    for (int o = 16; o > 0; o >>= 1) m = fmaxf(m, __shfl_xor_sync(0xffffffffu, m, o));
    if ((t & 31) == 0) red[t >> 5] = m;
    __syncthreads();
    m = red[0];
    #pragma unroll
    for (int w = 1; w < 8; w++) m = fmaxf(m, red[w]);

    v.x = __expf(v.x - m); v.y = __expf(v.y - m);
    v.z = __expf(v.z - m); v.w = __expf(v.w - m);
    float s = v.x + v.y + v.z + v.w;
    #pragma unroll
    for (int o = 16; o > 0; o >>= 1) s += __shfl_xor_sync(0xffffffffu, s, o);
    __syncthreads();
    if ((t & 31) == 0) red[t >> 5] = s;
    __syncthreads();
    s = 0.0f;
    #pragma unroll
    for (int w = 0; w < 8; w++) s += red[w];

    float inv = 1.0f / s;
    *(__half2*)&prow[t * 4]     = __floats2half2_rn(v.x * inv, v.y * inv);
    *(__half2*)&prow[t * 4 + 2] = __floats2half2_rn(v.z * inv, v.w * inv);
}

// ---------------------------------------------------------------------------
// Fused residual + LayerNorm, dual fp32 + fp16 output
// ---------------------------------------------------------------------------
__global__ void __launch_bounds__(256) ln_k(
    const float* __restrict__ a, const float* __restrict__ res,
    const float* __restrict__ sg, const float* __restrict__ bg,
    float* __restrict__ outF, __half* __restrict__ outH)
{
    long r = blockIdx.x;
    int  t = threadIdx.x;
    float v = a[r * Dc + t] + res[r * Dc + t];

    __shared__ float red[8];

    float s = v;
    #pragma unroll
    for (int o = 16; o > 0; o >>= 1) s += __shfl_xor_sync(0xffffffffu, s, o);
    if ((t & 31) == 0) red[t >> 5] = s;
    __syncthreads();
    s = 0.0f;
    #pragma unroll
    for (int w = 0; w < 8; w++) s += red[w];
    float mean = s * (1.0f / Dc);

    float d = v - mean;
    float q = d * d;
    #pragma unroll
    for (int o = 16; o > 0; o >>= 1) q += __shfl_xor_sync(0xffffffffu, q, o);
    __syncthreads();
    if ((t & 31) == 0) red[t >> 5] = q;
    __syncthreads();
    q = 0.0f;
    #pragma unroll
    for (int w = 0; w < 8; w++) q += red[w];
    float var = q * (1.0f / Dc);

    float o = d * rsqrtf(var + LN_EPS) * sg[t] + bg[t];
    outF[r * Dc + t] = o;
    outH[r * Dc + t] = __float2half_rn(o);
}

// ---------------------------------------------------------------------------
// Split-K reduce (4 slabs) + bias + residual + LayerNorm, dual output.
// ---------------------------------------------------------------------------
__global__ void __launch_bounds__(256) ln4_k(
    const float* __restrict__ part, const float* __restrict__ bias,
    const float* __restrict__ res,
    const float* __restrict__ sg, const float* __restrict__ bg,
    float* __restrict__ outF, __half* __restrict__ outH)
{
    long r = blockIdx.x;
    int  t = threadIdx.x;
    long i = r * Dc + t;
    const long S = (long)NROWS * Dc;
    float v = part[i] + part[i + S] + part[i + 2*S] + part[i + 3*S]
            + bias[t] + res[i];

    __shared__ float red[8];

    float s = v;
    #pragma unroll
    for (int o = 16; o > 0; o >>= 1) s += __shfl_xor_sync(0xffffffffu, s, o);
    if ((t & 31) == 0) red[t >> 5] = s;
    __syncthreads();
    s = 0.0f;
    #pragma unroll
    for (int w = 0; w < 8; w++) s += red[w];
    float mean = s * (1.0f / Dc);

    float d = v - mean;
    float q = d * d;
    #pragma unroll
    for (int o = 16; o > 0; o >>= 1) q += __shfl_xor_sync(0xffffffffu, q, o);
    __syncthreads();
    if ((t & 31) == 0) red[t >> 5] = q;
    __syncthreads();
    q = 0.0f;
    #pragma unroll
    for (int w = 0; w < 8; w++) q += red[w];
    float var = q * (1.0f / Dc);

    float o = d * rsqrtf(var + LN_EPS) * sg[t] + bg[t];
    outF[i] = o;
    outH[i] = __float2half_rn(o);
}

// ---------------------------------------------------------------------------
// Launch
// ---------------------------------------------------------------------------
extern "C" void kernel_launch(void* const* d_in, const int* in_sizes, int n_in,
                              void* d_out, int out_size)
{
    const float* queries = (const float*)d_in[0];
    const float* Wq   = (const float*)d_in[1];
    const float* bq   = (const float*)d_in[2];
    const float* Wk   = (const float*)d_in[3];
    const float* bk   = (const float*)d_in[4];
    const float* Wv   = (const float*)d_in[5];
    const float* bv   = (const float*)d_in[6];
    const float* Wo   = (const float*)d_in[7];
    const float* bo   = (const float*)d_in[8];
    const float* ln1s = (const float*)d_in[9];
    const float* ln1b = (const float*)d_in[10];
    const float* W1   = (const float*)d_in[11];
    const float* b1   = (const float*)d_in[12];
    const float* W2   = (const float*)d_in[13];
    const float* b2   = (const float*)d_in[14];
    const float* ln2s = (const float*)d_in[15];
    const float* ln2b = (const float*)d_in[16];

    float *x, *part, *sc, *bqkv;
    __half *xh, *qkvh, *aoh, *hh, *ph;
    __half *wqkvh, *woh, *w1h, *w2h;
    cudaGetSymbolAddress((void**)&x,     g_x);
    cudaGetSymbolAddress((void**)&part,  g_part);
    cudaGetSymbolAddress((void**)&sc,    g_s);
    cudaGetSymbolAddress((void**)&bqkv,  g_bqkv);
    cudaGetSymbolAddress((void**)&xh,    g_xh);
    cudaGetSymbolAddress((void**)&qkvh,  g_qkvh);
    cudaGetSymbolAddress((void**)&aoh,   g_aoh);
    cudaGetSymbolAddress((void**)&hh,    g_hh);
    cudaGetSymbolAddress((void**)&ph,    g_ph);
    cudaGetSymbolAddress((void**)&wqkvh, g_wqkvh);
    cudaGetSymbolAddress((void**)&woh,   g_woh);
    cudaGetSymbolAddress((void**)&w1h,   g_w1h);
    cudaGetSymbolAddress((void**)&w2h,   g_w2h);

    const int SMH_T = 2 * (128*144 + 64*272);   // 71680
    const int SMH_F = 2 * (128*144 + 128*144);  // 73728
    cudaFuncSetAttribute(gemm_h<true>,  cudaFuncAttributeMaxDynamicSharedMemorySize, SMH_T);
    cudaFuncSetAttribute(gemm_h<false>, cudaFuncAttributeMaxDynamicSharedMemorySize, SMH_F);

    const float* xin = queries;
    const float qscale = 1.0f / 16.0f;

    cvt_all_k<<<4102, 256>>>(queries, Wq, Wk, Wv, Wo, W1, W2, bq, bk, bv);

    __half* qh = qkvh;
    __half* kh = qkvh + (long)NROWS * HD;
    __half* vh = qkvh + 2L * NROWS * HD;

    for (int l = 0; l < Lc; l++) {
        const __half* wqkv = wqkvh + (long)l * 3 * Dc * HD;
        const __half* wo = woh + (long)l * HD * Dc;
        const __half* w1 = w1h + (long)l * Dc * Mc;
        const __half* w2 = w2h + (long)l * Mc * Dc;
        const float* bql3 = bqkv + (long)l * 3 * HD;
        const float* bol = bo + (long)l * Dc;
        const float* b1l = b1 + (long)l * Mc;
        const float* b2l = b2 + (long)l * Dc;
        const float* s1l = ln1s + (long)l * Dc;
        const float* o1l = ln1b + (long)l * Dc;
        const float* s2l = ln2s + (long)l * Dc;
        const float* o2l = ln2b + (long)l * Dc;

        // Fused QKV (768 CTAs, K=256)
        gemm_h<true><<<dim3(HD/128, NROWS/128, 3), 256, SMH_T>>>(
            xh, wqkv, nullptr, qkvh, bql3, Dc, Dc, HD, HD,
            0, 0, (long)Dc*HD, 0, (long)NROWS*HD, 0, (long)HD,
            1, 1.0f, 0);

        // scores = (q @ k^T) * qscale  (1024 CTAs, K=256)
        gemm_h<false><<<dim3(Tc/128, Tc/128, Bc*Hc), 256, SMH_F>>>(
            qh, kh, sc, nullptr, nullptr, Dc, HD, HD, Tc,
            (long)Tc*HD, (long)Dc,
            (long)Tc*HD, (long)Dc,
            (long)Hc*Tc*Tc, (long)Tc*Tc, 0,
            Hc, qscale, 0);

        softmax_k<<<Bc*Hc*Tc, 256>>>(sc, ph);

        // PV: probs @ V  (256 CTAs, K=1024)
        gemm_h<true><<<dim3(Dc/128, Tc/128, Bc*Hc), 256, SMH_T>>>(
            ph, vh, nullptr, aoh, nullptr, Tc, Tc, HD, HD,
            (long)Hc*Tc*Tc, (long)Tc*Tc,
            (long)Tc*HD, (long)Dc,
            (long)Tc*HD, (long)Dc, 0,
            Hc, 1.0f, 0);

        // Wo split-K=4: z advances K by 256; partial slabs; bias in ln4_k.
        gemm_h<true><<<dim3(Dc/128, NROWS/128, 4), 256, SMH_T>>>(
            aoh, wo, part, nullptr, nullptr, 256, HD, Dc, Dc,
            256L, 0, 256L*Dc, 0, (long)NROWS*Dc, 0, 0,
            1, 1.0f, 0);

        ln4_k<<<NROWS, 256>>>(part, bol, xin, s1l, o1l, x, xh);

        // MLP1: [4096,256]x[256,1024] ReLU  (256 CTAs big tile)
        gemm_h<true><<<dim3(Mc/128, NROWS/128, 1), 256, SMH_T>>>(
            xh, w1, nullptr, hh, b1l, Dc, Dc, Mc, Mc,
            0,0,0,0,0,0,0, 1, 1.0f, 2);

        // MLP2 split-K=4: hh [4096,1024] x w2 [1024,256]
        gemm_h<true><<<dim3(Dc/128, NROWS/128, 4), 256, SMH_T>>>(
            hh, w2, part, nullptr, nullptr, 256, Mc, Dc, Dc,
            256L, 0, 256L*Dc, 0, (long)NROWS*Dc, 0, 0,
            1, 1.0f, 0);

        float* lnout = (l == Lc - 1) ? (float*)d_out : x;
        ln4_k<<<NROWS, 256>>>(part, b2l, x, s2l, o2l, lnout, xh);

        xin = x;
    }
}

// round 10
// speedup vs baseline: 1.2490x; 1.0866x over previous
#include <cuda_runtime.h>
#include <cuda_fp16.h>
#include <cstdint>
#include <math.h>

// Problem constants
#define Lc 2
#define Bc 4
#define Tc 1024
#define Dc 256
#define Hc 4
#define Mc 1024
#define NROWS (Bc*Tc)      // 4096
#define HD (Hc*Dc)         // 1024
#define LN_EPS 1e-5f

// ---------------------------------------------------------------------------
// Scratch (device globals; allocation-free contract)
// ---------------------------------------------------------------------------
__device__ float  g_x[NROWS*Dc];
__device__ float  g_part[4L*NROWS*Dc];         // split-K partials (16MB)
__device__ float  g_s[(long)Bc*Hc*Tc*Tc];      // fp32 attention scores (64MB)
__device__ float  g_bqkv[Lc*3*HD];             // packed QKV biases
__device__ __half g_xh[NROWS*Dc];
__device__ __half g_qkvh[3L*NROWS*HD];         // q | k | v contiguous
__device__ __half g_aoh[NROWS*HD];
__device__ __half g_hh[NROWS*Mc];
__device__ __half g_ph[(long)Bc*Hc*Tc*Tc];     // half probs (32MB)
__device__ __half g_wqkvh[Lc*3*Dc*HD];         // [l][q,k,v][D*HD]
__device__ __half g_woh[Lc*HD*Dc];
__device__ __half g_w1h[Lc*Dc*Mc];
__device__ __half g_w2h[Lc*Mc*Dc];

// ---------------------------------------------------------------------------
// Helpers
// ---------------------------------------------------------------------------
__device__ __forceinline__ uint32_t smem_u32(const void* p) {
    uint32_t a;
    asm("{ .reg .u64 t; cvta.to.shared.u64 t, %1; cvt.u32.u64 %0, t; }"
        : "=r"(a) : "l"(p));
    return a;
}
__device__ __forceinline__ void cp16(uint32_t dst, const void* src) {
    asm volatile("cp.async.cg.shared.global [%0], [%1], 16;"
                 :: "r"(dst), "l"(src) : "memory");
}
#define CP_COMMIT() asm volatile("cp.async.commit_group;" ::: "memory")
#define CP_WAIT(n)  asm volatile("cp.async.wait_group %0;" :: "n"(n) : "memory")

#define LDSM4(r, addr) \
    asm volatile("ldmatrix.sync.aligned.m8n8.x4.shared.b16 {%0,%1,%2,%3}, [%4];" \
        : "=r"((r)[0]), "=r"((r)[1]), "=r"((r)[2]), "=r"((r)[3]) : "r"(addr))
#define LDSM4T(r, addr) \
    asm volatile("ldmatrix.sync.aligned.m8n8.x4.trans.shared.b16 {%0,%1,%2,%3}, [%4];" \
        : "=r"((r)[0]), "=r"((r)[1]), "=r"((r)[2]), "=r"((r)[3]) : "r"(addr))

__device__ __forceinline__ void mma_f16(float* c, const uint32_t* a,
                                        uint32_t b0, uint32_t b1) {
    asm volatile(
        "mma.sync.aligned.m16n8k16.row.col.f32.f16.f16.f32 "
        "{%0,%1,%2,%3}, {%4,%5,%6,%7}, {%8,%9}, {%0,%1,%2,%3};"
        : "+f"(c[0]), "+f"(c[1]), "+f"(c[2]), "+f"(c[3])
        : "r"(a[0]), "r"(a[1]), "r"(a[2]), "r"(a[3]), "r"(b0), "r"(b1));
}

// ---------------------------------------------------------------------------
// Big-tile fp16 mma GEMM, BK=64. 128x128 CTA tile, 8 warps, 2-stage cp.async.
//   TB=false: B is [N,K] K-major -> ldmatrix
//   TB=true : B is [K,N] N-major -> ldmatrix.trans
// flags bit1 = ReLU. Cf (fp32) / Ch (half), either may be null.
// blockIdx.z: z = zq*zdiv + zr; offsets via per-operand strides; split-K is
// expressed by advancing A/B along K per z and writing partial slabs via sC1.
// ---------------------------------------------------------------------------
template<bool TB>
__global__ void __launch_bounds__(256, 2) gemm_h(
    const __half* __restrict__ A, const __half* __restrict__ B,
    float* __restrict__ Cf, __half* __restrict__ Ch, const float* __restrict__ bias,
    int K, int lda, int ldb, int ldc,
    long sA1, long sA2, long sB1, long sB2, long sC1, long sC2, long sBias,
    int zdiv, float alpha, int flags)
{
    constexpr int ASZ = 128 * 144;                    // 18432
    constexpr int BSZ2 = TB ? 64 * 272 : 128 * 144;
    constexpr int STG = ASZ + BSZ2;

    extern __shared__ char smem[];
    uint32_t sbase = smem_u32(smem);

    int z  = blockIdx.z;
    int zq = z / zdiv, zr = z % zdiv;
    A  += (long)zq * sA1 + (long)zr * sA2;
    B  += (long)zq * sB1 + (long)zr * sB2;
    if (Cf)   Cf   += (long)zq * sC1 + (long)zr * sC2;
    if (Ch)   Ch   += (long)zq * sC1 + (long)zr * sC2;
    if (bias) bias += (long)zq * sBias;

    int t    = threadIdx.x;
    int lane = t & 31, w = t >> 5;
    int rowBase = blockIdx.y * 128;
    int colBase = blockIdx.x * 128;

    const __half* pA0 = A + (long)(rowBase + (t >> 3)) * lda + (t & 7) * 8;
    uint32_t sa0 = (uint32_t)((t >> 3) * 144 + (t & 7) * 16);
    const __half* pB0;
    uint32_t sb0;
    if (TB) {
        pB0 = B + (long)(t >> 4) * ldb + colBase + (t & 15) * 8;
        sb0 = (uint32_t)((t >> 4) * 272 + (t & 15) * 16);
    } else {
        pB0 = B + (long)(colBase + (t >> 3)) * ldb + (t & 7) * 8;
        sb0 = (uint32_t)((t >> 3) * 144 + (t & 7) * 16);
    }
    const long bChunk = TB ? 64L * ldb : 64L;
    const long bStepG = TB ? 16L * ldb : 32L * ldb;
    const uint32_t bStepS = TB ? 16u * 272 : 32u * 144;

    int NC = K >> 6;

    {   // prologue
        #pragma unroll
        for (int i = 0; i < 4; i++) {
            cp16(sbase + sa0 + i * (32u * 144), pA0 + (long)i * 32 * lda);
            cp16(sbase + ASZ + sb0 + i * bStepS, pB0 + (long)i * bStepG);
        }
        CP_COMMIT();
    }

    int mb = (w & 3) * 32, nb = (w >> 2) * 64;
    int g  = lane >> 3, lr = lane & 7;
    int qr = lane >> 2, cl = lane & 3;

    float acc[2][8][4];
    #pragma unroll
    for (int i = 0; i < 2; i++)
        #pragma unroll
        for (int j = 0; j < 8; j++)
            #pragma unroll
            for (int u = 0; u < 4; u++) acc[i][j][u] = 0.0f;

    for (int c = 0; c < NC; c++) {
        int st = c & 1;
        if (c + 1 < NC) {
            uint32_t base = sbase + ((c + 1) & 1) * STG;
            const __half* pAc = pA0 + (c + 1) * 64;
            const __half* pBc = pB0 + (c + 1) * bChunk;
            #pragma unroll
            for (int i = 0; i < 4; i++) {
                cp16(base + sa0 + i * (32u * 144), pAc + (long)i * 32 * lda);
                cp16(base + ASZ + sb0 + i * bStepS, pBc + (long)i * bStepG);
            }
            CP_COMMIT();
            CP_WAIT(1);
        } else {
            CP_WAIT(0);
        }
        __syncthreads();

        uint32_t As = sbase + st * STG;
        uint32_t Bs = As + ASZ;

        #pragma unroll
        for (int kk = 0; kk < 64; kk += 16) {
            uint32_t af[2][4];
            #pragma unroll
            for (int mt = 0; mt < 2; mt++) {
                uint32_t addr = As + (uint32_t)((mb + mt * 16 + (g & 1) * 8 + lr) * 144
                                                + ((g >> 1) * 8 + kk) * 2);
                LDSM4(af[mt], addr);
            }
            #pragma unroll
            for (int np = 0; np < 4; np++) {
                uint32_t bf[4];
                if (TB) {
                    uint32_t addr = Bs + (uint32_t)((kk + (g & 1) * 8 + lr) * 272
                                                    + (nb + np * 16 + (g >> 1) * 8) * 2);
                    LDSM4T(bf, addr);
                } else {
                    uint32_t addr = Bs + (uint32_t)((nb + np * 16 + (g >> 1) * 8 + lr) * 144
                                                    + ((g & 1) * 8 + kk) * 2);
                    LDSM4(bf, addr);
                }
                mma_f16(acc[0][np * 2 + 0], af[0], bf[0], bf[1]);
                mma_f16(acc[0][np * 2 + 1], af[0], bf[2], bf[3]);
                mma_f16(acc[1][np * 2 + 0], af[1], bf[0], bf[1]);
                mma_f16(acc[1][np * 2 + 1], af[1], bf[2], bf[3]);
            }
        }
        __syncthreads();
    }

    #pragma unroll
    for (int mt = 0; mt < 2; mt++) {
        int r0 = rowBase + mb + mt * 16 + qr;
        #pragma unroll
        for (int nt = 0; nt < 8; nt++) {
            int c0 = colBase + nb + nt * 8 + cl * 2;
            float b0 = 0.0f, b1 = 0.0f;
            if (bias) { b0 = bias[c0]; b1 = bias[c0 + 1]; }
            float v0 = (acc[mt][nt][0] + b0) * alpha;
            float v1 = (acc[mt][nt][1] + b1) * alpha;
            float v2 = (acc[mt][nt][2] + b0) * alpha;
            float v3 = (acc[mt][nt][3] + b1) * alpha;
            if (flags & 2) {
                v0 = fmaxf(v0, 0.0f); v1 = fmaxf(v1, 0.0f);
                v2 = fmaxf(v2, 0.0f); v3 = fmaxf(v3, 0.0f);
            }
            if (Cf) {
                *(float2*)&Cf[(long)r0 * ldc + c0]       = make_float2(v0, v1);
                *(float2*)&Cf[(long)(r0 + 8) * ldc + c0] = make_float2(v2, v3);
            }
            if (Ch) {
                *(__half2*)&Ch[(long)r0 * ldc + c0]       = __floats2half2_rn(v0, v1);
                *(__half2*)&Ch[(long)(r0 + 8) * ldc + c0] = __floats2half2_rn(v2, v3);
            }
        }
    }
}

// ---------------------------------------------------------------------------
// One-shot convert/pack kernel (Round-6 layout).
// ---------------------------------------------------------------------------
__global__ void __launch_bounds__(256) cvt_all_k(
    const float* __restrict__ qf,
    const float* __restrict__ Wq, const float* __restrict__ Wk,
    const float* __restrict__ Wv, const float* __restrict__ Wo,
    const float* __restrict__ W1, const float* __restrict__ W2,
    const float* __restrict__ bq, const float* __restrict__ bk,
    const float* __restrict__ bv)
{
    int b = blockIdx.x;
    int tid = threadIdx.x;

    if (b >= 4096) {
        int j = b - 4096;
        int l = j / 3, tt = j % 3;
        const float* src = (tt == 0 ? bq : tt == 1 ? bk : bv) + (long)l * HD;
        float* dst = g_bqkv + (long)(l * 3 + tt) * HD;
        *(float4*)&dst[tid * 4] = *(const float4*)&src[tid * 4];
        return;
    }

    const float* src; __half* dst; long off;
    if (b < 1024) {
        src = qf; dst = g_xh; off = (long)b * 1024;
    } else if (b < 2560) {
        int i = b - 1024;
        int j = i >> 8;
        int r = i & 255;
        int l = j / 3, tt = j % 3;
        src = (tt == 0 ? Wq : tt == 1 ? Wk : Wv) + (long)l * Dc * HD;
        dst = g_wqkvh + (long)j * Dc * HD;
        off = (long)r * 1024;
    } else if (b < 3072) {
        src = Wo; dst = g_woh; off = (long)(b - 2560) * 1024;
    } else if (b < 3584) {
        src = W1; dst = g_w1h; off = (long)(b - 3072) * 1024;
    } else {
        src = W2; dst = g_w2h; off = (long)(b - 3584) * 1024;
    }
    long idx = off + tid * 4;
    float4 v = *(const float4*)&src[idx];
    *(__half2*)&dst[idx]     = __floats2half2_rn(v.x, v.y);
    *(__half2*)&dst[idx + 2] = __floats2half2_rn(v.z, v.w);
}

// ---------------------------------------------------------------------------
// Warp-per-row softmax: fp32 scores -> half probs. Row = Tc = 1024.
// 8 rows per 256-thread block; lane j-interleaved float4s; shuffle-only
// reductions (no smem, no __syncthreads).
// ---------------------------------------------------------------------------
__global__ void __launch_bounds__(256) softmax_k(const float* __restrict__ S,
                                                 __half* __restrict__ P)
{
    long wrow = (long)blockIdx.x * 8 + (threadIdx.x >> 5);
    int  l    = threadIdx.x & 31;
    const float* row = S + wrow * Tc;
    __half* prow = P + wrow * Tc;

    float4 v[8];
    #pragma unroll
    for (int j = 0; j < 8; j++)
        v[j] = *(const float4*)&row[j * 128 + l * 4];

    float m = -1e30f;
    #pragma unroll
    for (int j = 0; j < 8; j++)
        m = fmaxf(m, fmaxf(fmaxf(v[j].x, v[j].y), fmaxf(v[j].z, v[j].w)));
    #pragma unroll
    for (int o = 16; o > 0; o >>= 1)
        m = fmaxf(m, __shfl_xor_sync(0xffffffffu, m, o));

    float s = 0.0f;
    #pragma unroll
    for (int j = 0; j < 8; j++) {
        v[j].x = __expf(v[j].x - m); v[j].y = __expf(v[j].y - m);
        v[j].z = __expf(v[j].z - m); v[j].w = __expf(v[j].w - m);
        s += (v[j].x + v[j].y) + (v[j].z + v[j].w);
    }
    #pragma unroll
    for (int o = 16; o > 0; o >>= 1)
        s += __shfl_xor_sync(0xffffffffu, s, o);

    float inv = 1.0f / s;
    #pragma unroll
    for (int j = 0; j < 8; j++) {
        *(__half2*)&prow[j * 128 + l * 4]     = __floats2half2_rn(v[j].x * inv, v[j].y * inv);
        *(__half2*)&prow[j * 128 + l * 4 + 2] = __floats2half2_rn(v[j].z * inv, v[j].w * inv);
    }
}

// ---------------------------------------------------------------------------
// Warp-per-row fused residual + LayerNorm (D=256), dual fp32 + fp16 output.
// 8 rows per 256-thread block; shuffle-only reductions.
// ---------------------------------------------------------------------------
__global__ void __launch_bounds__(256) ln_k(
    const float* __restrict__ a, const float* __restrict__ res,
    const float* __restrict__ sg, const float* __restrict__ bg,
    float* __restrict__ outF, __half* __restrict__ outH)
{
    long wrow = (long)blockIdx.x * 8 + (threadIdx.x >> 5);
    int  l    = threadIdx.x & 31;
    long base = wrow * Dc;

    float4 v[2];
    #pragma unroll
    for (int j = 0; j < 2; j++) {
        float4 av = *(const float4*)&a[base + j * 128 + l * 4];
        float4 rv = *(const float4*)&res[base + j * 128 + l * 4];
        v[j] = make_float4(av.x + rv.x, av.y + rv.y, av.z + rv.z, av.w + rv.w);
    }

    float s = (v[0].x + v[0].y + v[0].z + v[0].w)
            + (v[1].x + v[1].y + v[1].z + v[1].w);
    #pragma unroll
    for (int o = 16; o > 0; o >>= 1) s += __shfl_xor_sync(0xffffffffu, s, o);
    float mean = s * (1.0f / Dc);

    float q = 0.0f;
    #pragma unroll
    for (int j = 0; j < 2; j++) {
        float dx = v[j].x - mean, dy = v[j].y - mean;
        float dz = v[j].z - mean, dw = v[j].w - mean;
        q += dx*dx + dy*dy + dz*dz + dw*dw;
    }
    #pragma unroll
    for (int o = 16; o > 0; o >>= 1) q += __shfl_xor_sync(0xffffffffu, q, o);
    float rstd = rsqrtf(q * (1.0f / Dc) + LN_EPS);

    #pragma unroll
    for (int j = 0; j < 2; j++) {
        int c = j * 128 + l * 4;
        float o0 = (v[j].x - mean) * rstd * sg[c]     + bg[c];
        float o1 = (v[j].y - mean) * rstd * sg[c + 1] + bg[c + 1];
        float o2 = (v[j].z - mean) * rstd * sg[c + 2] + bg[c + 2];
        float o3 = (v[j].w - mean) * rstd * sg[c + 3] + bg[c + 3];
        *(float4*)&outF[base + c] = make_float4(o0, o1, o2, o3);
        *(__half2*)&outH[base + c]     = __floats2half2_rn(o0, o1);
        *(__half2*)&outH[base + c + 2] = __floats2half2_rn(o2, o3);
    }
}

// ---------------------------------------------------------------------------
// Warp-per-row split-K reduce (4 slabs) + bias + residual + LayerNorm.
// ---------------------------------------------------------------------------
__global__ void __launch_bounds__(256) ln4_k(
    const float* __restrict__ part, const float* __restrict__ bias,
    const float* __restrict__ res,
    const float* __restrict__ sg, const float* __restrict__ bg,
    float* __restrict__ outF, __half* __restrict__ outH)
{
    long wrow = (long)blockIdx.x * 8 + (threadIdx.x >> 5);
    int  l    = threadIdx.x & 31;
    long base = wrow * Dc;
    const long SS = (long)NROWS * Dc;

    float4 v[2];
    #pragma unroll
    for (int j = 0; j < 2; j++) {
        long i = base + j * 128 + l * 4;
        float4 p0 = *(const float4*)&part[i];
        float4 p1 = *(const float4*)&part[i + SS];
        float4 p2 = *(const float4*)&part[i + 2*SS];
        float4 p3 = *(const float4*)&part[i + 3*SS];
        float4 rv = *(const float4*)&res[i];
        int c = j * 128 + l * 4;
        v[j] = make_float4(p0.x + p1.x + p2.x + p3.x + bias[c]     + rv.x,
                           p0.y + p1.y + p2.y + p3.y + bias[c + 1] + rv.y,
                           p0.z + p1.z + p2.z + p3.z + bias[c + 2] + rv.z,
                           p0.w + p1.w + p2.w + p3.w + bias[c + 3] + rv.w);
    }

    float s = (v[0].x + v[0].y + v[0].z + v[0].w)
            + (v[1].x + v[1].y + v[1].z + v[1].w);
    #pragma unroll
    for (int o = 16; o > 0; o >>= 1) s += __shfl_xor_sync(0xffffffffu, s, o);
    float mean = s * (1.0f / Dc);

    float q = 0.0f;
    #pragma unroll
    for (int j = 0; j < 2; j++) {
        float dx = v[j].x - mean, dy = v[j].y - mean;
        float dz = v[j].z - mean, dw = v[j].w - mean;
        q += dx*dx + dy*dy + dz*dz + dw*dw;
    }
    #pragma unroll
    for (int o = 16; o > 0; o >>= 1) q += __shfl_xor_sync(0xffffffffu, q, o);
    float rstd = rsqrtf(q * (1.0f / Dc) + LN_EPS);

    #pragma unroll
    for (int j = 0; j < 2; j++) {
        int c = j * 128 + l * 4;
        float o0 = (v[j].x - mean) * rstd * sg[c]     + bg[c];
        float o1 = (v[j].y - mean) * rstd * sg[c + 1] + bg[c + 1];
        float o2 = (v[j].z - mean) * rstd * sg[c + 2] + bg[c + 2];
        float o3 = (v[j].w - mean) * rstd * sg[c + 3] + bg[c + 3];
        *(float4*)&outF[base + c] = make_float4(o0, o1, o2, o3);
        *(__half2*)&outH[base + c]     = __floats2half2_rn(o0, o1);
        *(__half2*)&outH[base + c + 2] = __floats2half2_rn(o2, o3);
    }
}

// ---------------------------------------------------------------------------
// Launch
// ---------------------------------------------------------------------------
extern "C" void kernel_launch(void* const* d_in, const int* in_sizes, int n_in,
                              void* d_out, int out_size)
{
    const float* queries = (const float*)d_in[0];
    const float* Wq   = (const float*)d_in[1];
    const float* bq   = (const float*)d_in[2];
    const float* Wk   = (const float*)d_in[3];
    const float* bk   = (const float*)d_in[4];
    const float* Wv   = (const float*)d_in[5];
    const float* bv   = (const float*)d_in[6];
    const float* Wo   = (const float*)d_in[7];
    const float* bo   = (const float*)d_in[8];
    const float* ln1s = (const float*)d_in[9];
    const float* ln1b = (const float*)d_in[10];
    const float* W1   = (const float*)d_in[11];
    const float* b1   = (const float*)d_in[12];
    const float* W2   = (const float*)d_in[13];
    const float* b2   = (const float*)d_in[14];
    const float* ln2s = (const float*)d_in[15];
    const float* ln2b = (const float*)d_in[16];

    float *x, *part, *sc, *bqkv;
    __half *xh, *qkvh, *aoh, *hh, *ph;
    __half *wqkvh, *woh, *w1h, *w2h;
    cudaGetSymbolAddress((void**)&x,     g_x);
    cudaGetSymbolAddress((void**)&part,  g_part);
    cudaGetSymbolAddress((void**)&sc,    g_s);
    cudaGetSymbolAddress((void**)&bqkv,  g_bqkv);
    cudaGetSymbolAddress((void**)&xh,    g_xh);
    cudaGetSymbolAddress((void**)&qkvh,  g_qkvh);
    cudaGetSymbolAddress((void**)&aoh,   g_aoh);
    cudaGetSymbolAddress((void**)&hh,    g_hh);
    cudaGetSymbolAddress((void**)&ph,    g_ph);
    cudaGetSymbolAddress((void**)&wqkvh, g_wqkvh);
    cudaGetSymbolAddress((void**)&woh,   g_woh);
    cudaGetSymbolAddress((void**)&w1h,   g_w1h);
    cudaGetSymbolAddress((void**)&w2h,   g_w2h);

    const int SMH_T = 2 * (128*144 + 64*272);   // 71680
    const int SMH_F = 2 * (128*144 + 128*144);  // 73728
    cudaFuncSetAttribute(gemm_h<true>,  cudaFuncAttributeMaxDynamicSharedMemorySize, SMH_T);
    cudaFuncSetAttribute(gemm_h<false>, cudaFuncAttributeMaxDynamicSharedMemorySize, SMH_F);

    const float* xin = queries;
    const float qscale = 1.0f / 16.0f;

    cvt_all_k<<<4102, 256>>>(queries, Wq, Wk, Wv, Wo, W1, W2, bq, bk, bv);

    __half* qh = qkvh;
    __half* kh = qkvh + (long)NROWS * HD;
    __half* vh = qkvh + 2L * NROWS * HD;

    for (int l = 0; l < Lc; l++) {
        const __half* wqkv = wqkvh + (long)l * 3 * Dc * HD;
        const __half* w1 = w1h + (long)l * Dc * Mc;
        const __half* w2 = w2h + (long)l * Mc * Dc;
        const __half* wo = woh + (long)l * HD * Dc;
        const float* bql3 = bqkv + (long)l * 3 * HD;
        const float* bol = bo + (long)l * Dc;
        const float* b1l = b1 + (long)l * Mc;
        const float* b2l = b2 + (long)l * Dc;
        const float* s1l = ln1s + (long)l * Dc;
        const float* o1l = ln1b + (long)l * Dc;
        const float* s2l = ln2s + (long)l * Dc;
        const float* o2l = ln2b + (long)l * Dc;

        // Fused QKV (768 CTAs, K=256)
        gemm_h<true><<<dim3(HD/128, NROWS/128, 3), 256, SMH_T>>>(
            xh, wqkv, nullptr, qkvh, bql3, Dc, Dc, HD, HD,
            0, 0, (long)Dc*HD, 0, (long)NROWS*HD, 0, (long)HD,
            1, 1.0f, 0);

        // scores = (q @ k^T) * qscale  (1024 CTAs, K=256)
        gemm_h<false><<<dim3(Tc/128, Tc/128, Bc*Hc), 256, SMH_F>>>(
            qh, kh, sc, nullptr, nullptr, Dc, HD, HD, Tc,
            (long)Tc*HD, (long)Dc,
            (long)Tc*HD, (long)Dc,
            (long)Hc*Tc*Tc, (long)Tc*Tc, 0,
            Hc, qscale, 0);

        softmax_k<<<Bc*Hc*Tc/8, 256>>>(sc, ph);

        // PV: probs @ V  (256 CTAs, K=1024)
        gemm_h<true><<<dim3(Dc/128, Tc/128, Bc*Hc), 256, SMH_T>>>(
            ph, vh, nullptr, aoh, nullptr, Tc, Tc, HD, HD,
            (long)Hc*Tc*Tc, (long)Tc*Tc,
            (long)Tc*HD, (long)Dc,
            (long)Tc*HD, (long)Dc, 0,
            Hc, 1.0f, 0);

        // Wo split-K=4
        gemm_h<true><<<dim3(Dc/128, NROWS/128, 4), 256, SMH_T>>>(
            aoh, wo, part, nullptr, nullptr, 256, HD, Dc, Dc,
            256L, 0, 256L*Dc, 0, (long)NROWS*Dc, 0, 0,
            1, 1.0f, 0);

        ln4_k<<<NROWS/8, 256>>>(part, bol, xin, s1l, o1l, x, xh);

        // MLP1: [4096,256]x[256,1024] ReLU
        gemm_h<true><<<dim3(Mc/128, NROWS/128, 1), 256, SMH_T>>>(
            xh, w1, nullptr, hh, b1l, Dc, Dc, Mc, Mc,
            0,0,0,0,0,0,0, 1, 1.0f, 2);

        // MLP2 split-K=4
        gemm_h<true><<<dim3(Dc/128, NROWS/128, 4), 256, SMH_T>>>(
            hh, w2, part, nullptr, nullptr, 256, Mc, Dc, Dc,
            256L, 0, 256L*Dc, 0, (long)NROWS*Dc, 0, 0,
            1, 1.0f, 0);

        float* lnout = (l == Lc - 1) ? (float*)d_out : x;
        ln4_k<<<NROWS/8, 256>>>(part, b2l, x, s2l, o2l, lnout, xh);

        xin = x;
    }
}

// round 11
// speedup vs baseline: 1.2521x; 1.0024x over previous
#include <cuda_runtime.h>
#include <cuda_fp16.h>
#include <cstdint>
#include <math.h>

// Problem constants
#define Lc 2
#define Bc 4
#define Tc 1024
#define Dc 256
#define Hc 4
#define Mc 1024
#define NROWS (Bc*Tc)      // 4096
#define HD (Hc*Dc)         // 1024
#define LN_EPS 1e-5f

// ---------------------------------------------------------------------------
// Scratch (device globals; allocation-free contract)
// ---------------------------------------------------------------------------
__device__ float  g_x[NROWS*Dc];
__device__ float  g_part[4L*NROWS*Dc];         // split-K partials (16MB)
__device__ float  g_s[(long)Bc*Hc*Tc*Tc];      // fp32 attention scores (64MB)
__device__ float  g_bqkv[Lc*3*HD];             // packed QKV biases
__device__ __half g_xh[NROWS*Dc];
__device__ __half g_qkvh[3L*NROWS*HD];         // q | k | v contiguous
__device__ __half g_aoh[NROWS*HD];
__device__ __half g_hh[NROWS*Mc];
__device__ __half g_ph[(long)Bc*Hc*Tc*Tc];     // half probs (32MB)
__device__ __half g_wqkvh[Lc*3*Dc*HD];         // [l][q,k,v][D*HD]
__device__ __half g_woh[Lc*HD*Dc];
__device__ __half g_w1h[Lc*Dc*Mc];
__device__ __half g_w2h[Lc*Mc*Dc];

// ---------------------------------------------------------------------------
// Helpers
// ---------------------------------------------------------------------------
__device__ __forceinline__ uint32_t smem_u32(const void* p) {
    uint32_t a;
    asm("{ .reg .u64 t; cvta.to.shared.u64 t, %1; cvt.u32.u64 %0, t; }"
        : "=r"(a) : "l"(p));
    return a;
}
__device__ __forceinline__ void cp16(uint32_t dst, const void* src) {
    asm volatile("cp.async.cg.shared.global [%0], [%1], 16;"
                 :: "r"(dst), "l"(src) : "memory");
}
#define CP_COMMIT() asm volatile("cp.async.commit_group;" ::: "memory")
#define CP_WAIT(n)  asm volatile("cp.async.wait_group %0;" :: "n"(n) : "memory")

#define LDSM4(r, addr) \
    asm volatile("ldmatrix.sync.aligned.m8n8.x4.shared.b16 {%0,%1,%2,%3}, [%4];" \
        : "=r"((r)[0]), "=r"((r)[1]), "=r"((r)[2]), "=r"((r)[3]) : "r"(addr))
#define LDSM4T(r, addr) \
    asm volatile("ldmatrix.sync.aligned.m8n8.x4.trans.shared.b16 {%0,%1,%2,%3}, [%4];" \
        : "=r"((r)[0]), "=r"((r)[1]), "=r"((r)[2]), "=r"((r)[3]) : "r"(addr))

__device__ __forceinline__ void mma_f16(float* c, const uint32_t* a,
                                        uint32_t b0, uint32_t b1) {
    asm volatile(
        "mma.sync.aligned.m16n8k16.row.col.f32.f16.f16.f32 "
        "{%0,%1,%2,%3}, {%4,%5,%6,%7}, {%8,%9}, {%0,%1,%2,%3};"
        : "+f"(c[0]), "+f"(c[1]), "+f"(c[2]), "+f"(c[3])
        : "r"(a[0]), "r"(a[1]), "r"(a[2]), "r"(a[3]), "r"(b0), "r"(b1));
}

// ---------------------------------------------------------------------------
// Big-tile fp16 mma GEMM, BK=64, 3-stage cp.async ring, ONE barrier/chunk.
// 128x128 CTA tile, 8 warps.
//   TB=false: B is [N,K] K-major -> ldmatrix
//   TB=true : B is [K,N] N-major -> ldmatrix.trans
// flags bit1 = ReLU. Cf (fp32) / Ch (half), either may be null.
// blockIdx.z: z = zq*zdiv + zr; split-K via K-advancing strides + sC1 slabs.
// ---------------------------------------------------------------------------
template<bool TB>
__global__ void __launch_bounds__(256, 2) gemm_h(
    const __half* __restrict__ A, const __half* __restrict__ B,
    float* __restrict__ Cf, __half* __restrict__ Ch, const float* __restrict__ bias,
    int K, int lda, int ldb, int ldc,
    long sA1, long sA2, long sB1, long sB2, long sC1, long sC2, long sBias,
    int zdiv, float alpha, int flags)
{
    constexpr int ASZ = 128 * 144;                    // 18432
    constexpr int BSZ2 = TB ? 64 * 272 : 128 * 144;
    constexpr int STG = ASZ + BSZ2;

    extern __shared__ char smem[];
    uint32_t sbase = smem_u32(smem);

    int z  = blockIdx.z;
    int zq = z / zdiv, zr = z % zdiv;
    A  += (long)zq * sA1 + (long)zr * sA2;
    B  += (long)zq * sB1 + (long)zr * sB2;
    if (Cf)   Cf   += (long)zq * sC1 + (long)zr * sC2;
    if (Ch)   Ch   += (long)zq * sC1 + (long)zr * sC2;
    if (bias) bias += (long)zq * sBias;

    int t    = threadIdx.x;
    int lane = t & 31, w = t >> 5;
    int rowBase = blockIdx.y * 128;
    int colBase = blockIdx.x * 128;

    const __half* pA0 = A + (long)(rowBase + (t >> 3)) * lda + (t & 7) * 8;
    uint32_t sa0 = (uint32_t)((t >> 3) * 144 + (t & 7) * 16);
    const __half* pB0;
    uint32_t sb0;
    if (TB) {
        pB0 = B + (long)(t >> 4) * ldb + colBase + (t & 15) * 8;
        sb0 = (uint32_t)((t >> 4) * 272 + (t & 15) * 16);
    } else {
        pB0 = B + (long)(colBase + (t >> 3)) * ldb + (t & 7) * 8;
        sb0 = (uint32_t)((t >> 3) * 144 + (t & 7) * 16);
    }
    const long bChunk = TB ? 64L * ldb : 64L;
    const long bStepG = TB ? 16L * ldb : 32L * ldb;
    const uint32_t bStepS = TB ? 16u * 272 : 32u * 144;

    int NC = K >> 6;

    // prologue: chunks 0,1 -> stages 0,1 (two groups in flight)
    {
        #pragma unroll
        for (int i = 0; i < 4; i++) {
            cp16(sbase + sa0 + i * (32u * 144), pA0 + (long)i * 32 * lda);
            cp16(sbase + ASZ + sb0 + i * bStepS, pB0 + (long)i * bStepG);
        }
        CP_COMMIT();
    }
    if (NC > 1) {
        uint32_t base = sbase + STG;
        #pragma unroll
        for (int i = 0; i < 4; i++) {
            cp16(base + sa0 + i * (32u * 144), pA0 + 64 + (long)i * 32 * lda);
            cp16(base + ASZ + sb0 + i * bStepS, pB0 + bChunk + (long)i * bStepG);
        }
        CP_COMMIT();
    }

    int mb = (w & 3) * 32, nb = (w >> 2) * 64;
    int g  = lane >> 3, lr = lane & 7;
    int qr = lane >> 2, cl = lane & 3;

    float acc[2][8][4];
    #pragma unroll
    for (int i = 0; i < 2; i++)
        #pragma unroll
        for (int j = 0; j < 8; j++)
            #pragma unroll
            for (int u = 0; u < 4; u++) acc[i][j][u] = 0.0f;

    int st = 0;   // stage of chunk c
    int ld = 2;   // stage for chunk c+2 (vacated by chunk c-1)
    for (int c = 0; c < NC; c++) {
        if (c + 1 < NC) { CP_WAIT(1); } else { CP_WAIT(0); }
        __syncthreads();   // chunk c resident; all warps finished chunk c-1

        if (c + 2 < NC) {
            uint32_t base = sbase + ld * STG;
            const __half* pAc = pA0 + (c + 2) * 64;
            const __half* pBc = pB0 + (c + 2) * bChunk;
            #pragma unroll
            for (int i = 0; i < 4; i++) {
                cp16(base + sa0 + i * (32u * 144), pAc + (long)i * 32 * lda);
                cp16(base + ASZ + sb0 + i * bStepS, pBc + (long)i * bStepG);
            }
            CP_COMMIT();
        }

        uint32_t As = sbase + st * STG;
        uint32_t Bs = As + ASZ;

        #pragma unroll
        for (int kk = 0; kk < 64; kk += 16) {
            uint32_t af[2][4];
            #pragma unroll
            for (int mt = 0; mt < 2; mt++) {
                uint32_t addr = As + (uint32_t)((mb + mt * 16 + (g & 1) * 8 + lr) * 144
                                                + ((g >> 1) * 8 + kk) * 2);
                LDSM4(af[mt], addr);
            }
            #pragma unroll
            for (int np = 0; np < 4; np++) {
                uint32_t bf[4];
                if (TB) {
                    uint32_t addr = Bs + (uint32_t)((kk + (g & 1) * 8 + lr) * 272
                                                    + (nb + np * 16 + (g >> 1) * 8) * 2);
                    LDSM4T(bf, addr);
                } else {
                    uint32_t addr = Bs + (uint32_t)((nb + np * 16 + (g >> 1) * 8 + lr) * 144
                                                    + ((g & 1) * 8 + kk) * 2);
                    LDSM4(bf, addr);
                }
                mma_f16(acc[0][np * 2 + 0], af[0], bf[0], bf[1]);
                mma_f16(acc[0][np * 2 + 1], af[0], bf[2], bf[3]);
                mma_f16(acc[1][np * 2 + 0], af[1], bf[0], bf[1]);
                mma_f16(acc[1][np * 2 + 1], af[1], bf[2], bf[3]);
            }
        }
        st = (st == 2) ? 0 : st + 1;
        ld = (ld == 2) ? 0 : ld + 1;
    }

    #pragma unroll
    for (int mt = 0; mt < 2; mt++) {
        int r0 = rowBase + mb + mt * 16 + qr;
        #pragma unroll
        for (int nt = 0; nt < 8; nt++) {
            int c0 = colBase + nb + nt * 8 + cl * 2;
            float b0 = 0.0f, b1 = 0.0f;
            if (bias) { b0 = bias[c0]; b1 = bias[c0 + 1]; }
            float v0 = (acc[mt][nt][0] + b0) * alpha;
            float v1 = (acc[mt][nt][1] + b1) * alpha;
            float v2 = (acc[mt][nt][2] + b0) * alpha;
            float v3 = (acc[mt][nt][3] + b1) * alpha;
            if (flags & 2) {
                v0 = fmaxf(v0, 0.0f); v1 = fmaxf(v1, 0.0f);
                v2 = fmaxf(v2, 0.0f); v3 = fmaxf(v3, 0.0f);
            }
            if (Cf) {
                *(float2*)&Cf[(long)r0 * ldc + c0]       = make_float2(v0, v1);
                *(float2*)&Cf[(long)(r0 + 8) * ldc + c0] = make_float2(v2, v3);
            }
            if (Ch) {
                *(__half2*)&Ch[(long)r0 * ldc + c0]       = __floats2half2_rn(v0, v1);
                *(__half2*)&Ch[(long)(r0 + 8) * ldc + c0] = __floats2half2_rn(v2, v3);
            }
        }
    }
}

// ---------------------------------------------------------------------------
// One-shot convert/pack kernel (Round-6 layout).
// ---------------------------------------------------------------------------
__global__ void __launch_bounds__(256) cvt_all_k(
    const float* __restrict__ qf,
    const float* __restrict__ Wq, const float* __restrict__ Wk,
    const float* __restrict__ Wv, const float* __restrict__ Wo,
    const float* __restrict__ W1, const float* __restrict__ W2,
    const float* __restrict__ bq, const float* __restrict__ bk,
    const float* __restrict__ bv)
{
    int b = blockIdx.x;
    int tid = threadIdx.x;

    if (b >= 4096) {
        int j = b - 4096;
        int l = j / 3, tt = j % 3;
        const float* src = (tt == 0 ? bq : tt == 1 ? bk : bv) + (long)l * HD;
        float* dst = g_bqkv + (long)(l * 3 + tt) * HD;
        *(float4*)&dst[tid * 4] = *(const float4*)&src[tid * 4];
        return;
    }

    const float* src; __half* dst; long off;
    if (b < 1024) {
        src = qf; dst = g_xh; off = (long)b * 1024;
    } else if (b < 2560) {
        int i = b - 1024;
        int j = i >> 8;
        int r = i & 255;
        int l = j / 3, tt = j % 3;
        src = (tt == 0 ? Wq : tt == 1 ? Wk : Wv) + (long)l * Dc * HD;
        dst = g_wqkvh + (long)j * Dc * HD;
        off = (long)r * 1024;
    } else if (b < 3072) {
        src = Wo; dst = g_woh; off = (long)(b - 2560) * 1024;
    } else if (b < 3584) {
        src = W1; dst = g_w1h; off = (long)(b - 3072) * 1024;
    } else {
        src = W2; dst = g_w2h; off = (long)(b - 3584) * 1024;
    }
    long idx = off + tid * 4;
    float4 v = *(const float4*)&src[idx];
    *(__half2*)&dst[idx]     = __floats2half2_rn(v.x, v.y);
    *(__half2*)&dst[idx + 2] = __floats2half2_rn(v.z, v.w);
}

// ---------------------------------------------------------------------------
// Warp-per-row softmax: fp32 scores -> half probs. Row = Tc = 1024.
// ---------------------------------------------------------------------------
__global__ void __launch_bounds__(256) softmax_k(const float* __restrict__ S,
                                                 __half* __restrict__ P)
{
    long wrow = (long)blockIdx.x * 8 + (threadIdx.x >> 5);
    int  l    = threadIdx.x & 31;
    const float* row = S + wrow * Tc;
    __half* prow = P + wrow * Tc;

    float4 v[8];
    #pragma unroll
    for (int j = 0; j < 8; j++)
        v[j] = *(const float4*)&row[j * 128 + l * 4];

    float m = -1e30f;
    #pragma unroll
    for (int j = 0; j < 8; j++)
        m = fmaxf(m, fmaxf(fmaxf(v[j].x, v[j].y), fmaxf(v[j].z, v[j].w)));
    #pragma unroll
    for (int o = 16; o > 0; o >>= 1)
        m = fmaxf(m, __shfl_xor_sync(0xffffffffu, m, o));

    float s = 0.0f;
    #pragma unroll
    for (int j = 0; j < 8; j++) {
        v[j].x = __expf(v[j].x - m); v[j].y = __expf(v[j].y - m);
        v[j].z = __expf(v[j].z - m); v[j].w = __expf(v[j].w - m);
        s += (v[j].x + v[j].y) + (v[j].z + v[j].w);
    }
    #pragma unroll
    for (int o = 16; o > 0; o >>= 1)
        s += __shfl_xor_sync(0xffffffffu, s, o);

    float inv = 1.0f / s;
    #pragma unroll
    for (int j = 0; j < 8; j++) {
        *(__half2*)&prow[j * 128 + l * 4]     = __floats2half2_rn(v[j].x * inv, v[j].y * inv);
        *(__half2*)&prow[j * 128 + l * 4 + 2] = __floats2half2_rn(v[j].z * inv, v[j].w * inv);
    }
}

// ---------------------------------------------------------------------------
// Warp-per-row fused residual + LayerNorm (D=256), dual fp32 + fp16 output.
// ---------------------------------------------------------------------------
__global__ void __launch_bounds__(256) ln_k(
    const float* __restrict__ a, const float* __restrict__ res,
    const float* __restrict__ sg, const float* __restrict__ bg,
    float* __restrict__ outF, __half* __restrict__ outH)
{
    long wrow = (long)blockIdx.x * 8 + (threadIdx.x >> 5);
    int  l    = threadIdx.x & 31;
    long base = wrow * Dc;

    float4 v[2];
    #pragma unroll
    for (int j = 0; j < 2; j++) {
        float4 av = *(const float4*)&a[base + j * 128 + l * 4];
        float4 rv = *(const float4*)&res[base + j * 128 + l * 4];
        v[j] = make_float4(av.x + rv.x, av.y + rv.y, av.z + rv.z, av.w + rv.w);
    }

    float s = (v[0].x + v[0].y + v[0].z + v[0].w)
            + (v[1].x + v[1].y + v[1].z + v[1].w);
    #pragma unroll
    for (int o = 16; o > 0; o >>= 1) s += __shfl_xor_sync(0xffffffffu, s, o);
    float mean = s * (1.0f / Dc);

    float q = 0.0f;
    #pragma unroll
    for (int j = 0; j < 2; j++) {
        float dx = v[j].x - mean, dy = v[j].y - mean;
        float dz = v[j].z - mean, dw = v[j].w - mean;
        q += dx*dx + dy*dy + dz*dz + dw*dw;
    }
    #pragma unroll
    for (int o = 16; o > 0; o >>= 1) q += __shfl_xor_sync(0xffffffffu, q, o);
    float rstd = rsqrtf(q * (1.0f / Dc) + LN_EPS);

    #pragma unroll
    for (int j = 0; j < 2; j++) {
        int c = j * 128 + l * 4;
        float o0 = (v[j].x - mean) * rstd * sg[c]     + bg[c];
        float o1 = (v[j].y - mean) * rstd * sg[c + 1] + bg[c + 1];
        float o2 = (v[j].z - mean) * rstd * sg[c + 2] + bg[c + 2];
        float o3 = (v[j].w - mean) * rstd * sg[c + 3] + bg[c + 3];
        *(float4*)&outF[base + c] = make_float4(o0, o1, o2, o3);
        *(__half2*)&outH[base + c]     = __floats2half2_rn(o0, o1);
        *(__half2*)&outH[base + c + 2] = __floats2half2_rn(o2, o3);
    }
}

// ---------------------------------------------------------------------------
// Warp-per-row split-K reduce (4 slabs) + bias + residual + LayerNorm.
// ---------------------------------------------------------------------------
__global__ void __launch_bounds__(256) ln4_k(
    const float* __restrict__ part, const float* __restrict__ bias,
    const float* __restrict__ res,
    const float* __restrict__ sg, const float* __restrict__ bg,
    float* __restrict__ outF, __half* __restrict__ outH)
{
    long wrow = (long)blockIdx.x * 8 + (threadIdx.x >> 5);
    int  l    = threadIdx.x & 31;
    long base = wrow * Dc;
    const long SS = (long)NROWS * Dc;

    float4 v[2];
    #pragma unroll
    for (int j = 0; j < 2; j++) {
        long i = base + j * 128 + l * 4;
        float4 p0 = *(const float4*)&part[i];
        float4 p1 = *(const float4*)&part[i + SS];
        float4 p2 = *(const float4*)&part[i + 2*SS];
        float4 p3 = *(const float4*)&part[i + 3*SS];
        float4 rv = *(const float4*)&res[i];
        int c = j * 128 + l * 4;
        v[j] = make_float4(p0.x + p1.x + p2.x + p3.x + bias[c]     + rv.x,
                           p0.y + p1.y + p2.y + p3.y + bias[c + 1] + rv.y,
                           p0.z + p1.z + p2.z + p3.z + bias[c + 2] + rv.z,
                           p0.w + p1.w + p2.w + p3.w + bias[c + 3] + rv.w);
    }

    float s = (v[0].x + v[0].y + v[0].z + v[0].w)
            + (v[1].x + v[1].y + v[1].z + v[1].w);
    #pragma unroll
    for (int o = 16; o > 0; o >>= 1) s += __shfl_xor_sync(0xffffffffu, s, o);
    float mean = s * (1.0f / Dc);

    float q = 0.0f;
    #pragma unroll
    for (int j = 0; j < 2; j++) {
        float dx = v[j].x - mean, dy = v[j].y - mean;
        float dz = v[j].z - mean, dw = v[j].w - mean;
        q += dx*dx + dy*dy + dz*dz + dw*dw;
    }
    #pragma unroll
    for (int o = 16; o > 0; o >>= 1) q += __shfl_xor_sync(0xffffffffu, q, o);
    float rstd = rsqrtf(q * (1.0f / Dc) + LN_EPS);

    #pragma unroll
    for (int j = 0; j < 2; j++) {
        int c = j * 128 + l * 4;
        float o0 = (v[j].x - mean) * rstd * sg[c]     + bg[c];
        float o1 = (v[j].y - mean) * rstd * sg[c + 1] + bg[c + 1];
        float o2 = (v[j].z - mean) * rstd * sg[c + 2] + bg[c + 2];
        float o3 = (v[j].w - mean) * rstd * sg[c + 3] + bg[c + 3];
        *(float4*)&outF[base + c] = make_float4(o0, o1, o2, o3);
        *(__half2*)&outH[base + c]     = __floats2half2_rn(o0, o1);
        *(__half2*)&outH[base + c + 2] = __floats2half2_rn(o2, o3);
    }
}

// ---------------------------------------------------------------------------
// Launch
// ---------------------------------------------------------------------------
extern "C" void kernel_launch(void* const* d_in, const int* in_sizes, int n_in,
                              void* d_out, int out_size)
{
    const float* queries = (const float*)d_in[0];
    const float* Wq   = (const float*)d_in[1];
    const float* bq   = (const float*)d_in[2];
    const float* Wk   = (const float*)d_in[3];
    const float* bk   = (const float*)d_in[4];
    const float* Wv   = (const float*)d_in[5];
    const float* bv   = (const float*)d_in[6];
    const float* Wo   = (const float*)d_in[7];
    const float* bo   = (const float*)d_in[8];
    const float* ln1s = (const float*)d_in[9];
    const float* ln1b = (const float*)d_in[10];
    const float* W1   = (const float*)d_in[11];
    const float* b1   = (const float*)d_in[12];
    const float* W2   = (const float*)d_in[13];
    const float* b2   = (const float*)d_in[14];
    const float* ln2s = (const float*)d_in[15];
    const float* ln2b = (const float*)d_in[16];

    float *x, *part, *sc, *bqkv;
    __half *xh, *qkvh, *aoh, *hh, *ph;
    __half *wqkvh, *woh, *w1h, *w2h;
    cudaGetSymbolAddress((void**)&x,     g_x);
    cudaGetSymbolAddress((void**)&part,  g_part);
    cudaGetSymbolAddress((void**)&sc,    g_s);
    cudaGetSymbolAddress((void**)&bqkv,  g_bqkv);
    cudaGetSymbolAddress((void**)&xh,    g_xh);
    cudaGetSymbolAddress((void**)&qkvh,  g_qkvh);
    cudaGetSymbolAddress((void**)&aoh,   g_aoh);
    cudaGetSymbolAddress((void**)&hh,    g_hh);
    cudaGetSymbolAddress((void**)&ph,    g_ph);
    cudaGetSymbolAddress((void**)&wqkvh, g_wqkvh);
    cudaGetSymbolAddress((void**)&woh,   g_woh);
    cudaGetSymbolAddress((void**)&w1h,   g_w1h);
    cudaGetSymbolAddress((void**)&w2h,   g_w2h);

    const int SMH_T = 3 * (128*144 + 64*272);   // 107520
    const int SMH_F = 3 * (128*144 + 128*144);  // 110592
    cudaFuncSetAttribute(gemm_h<true>,  cudaFuncAttributeMaxDynamicSharedMemorySize, SMH_T);
    cudaFuncSetAttribute(gemm_h<false>, cudaFuncAttributeMaxDynamicSharedMemorySize, SMH_F);

    const float* xin = queries;
    const float qscale = 1.0f / 16.0f;

    cvt_all_k<<<4102, 256>>>(queries, Wq, Wk, Wv, Wo, W1, W2, bq, bk, bv);

    __half* qh = qkvh;
    __half* kh = qkvh + (long)NROWS * HD;
    __half* vh = qkvh + 2L * NROWS * HD;

    for (int l = 0; l < Lc; l++) {
        const __half* wqkv = wqkvh + (long)l * 3 * Dc * HD;
        const __half* w1 = w1h + (long)l * Dc * Mc;
        const __half* w2 = w2h + (long)l * Mc * Dc;
        const __half* wo = woh + (long)l * HD * Dc;
        const float* bql3 = bqkv + (long)l * 3 * HD;
        const float* bol = bo + (long)l * Dc;
        const float* b1l = b1 + (long)l * Mc;
        const float* b2l = b2 + (long)l * Dc;
        const float* s1l = ln1s + (long)l * Dc;
        const float* o1l = ln1b + (long)l * Dc;
        const float* s2l = ln2s + (long)l * Dc;
        const float* o2l = ln2b + (long)l * Dc;

        // Fused QKV (768 CTAs, K=256)
        gemm_h<true><<<dim3(HD/128, NROWS/128, 3), 256, SMH_T>>>(
            xh, wqkv, nullptr, qkvh, bql3, Dc, Dc, HD, HD,
            0, 0, (long)Dc*HD, 0, (long)NROWS*HD, 0, (long)HD,
            1, 1.0f, 0);

        // scores = (q @ k^T) * qscale  (1024 CTAs, K=256)
        gemm_h<false><<<dim3(Tc/128, Tc/128, Bc*Hc), 256, SMH_F>>>(
            qh, kh, sc, nullptr, nullptr, Dc, HD, HD, Tc,
            (long)Tc*HD, (long)Dc,
            (long)Tc*HD, (long)Dc,
            (long)Hc*Tc*Tc, (long)Tc*Tc, 0,
            Hc, qscale, 0);

        softmax_k<<<Bc*Hc*Tc/8, 256>>>(sc, ph);

        // PV: probs @ V  (256 CTAs, K=1024)
        gemm_h<true><<<dim3(Dc/128, Tc/128, Bc*Hc), 256, SMH_T>>>(
            ph, vh, nullptr, aoh, nullptr, Tc, Tc, HD, HD,
            (long)Hc*Tc*Tc, (long)Tc*Tc,
            (long)Tc*HD, (long)Dc,
            (long)Tc*HD, (long)Dc, 0,
            Hc, 1.0f, 0);

        // Wo split-K=4
        gemm_h<true><<<dim3(Dc/128, NROWS/128, 4), 256, SMH_T>>>(
            aoh, wo, part, nullptr, nullptr, 256, HD, Dc, Dc,
            256L, 0, 256L*Dc, 0, (long)NROWS*Dc, 0, 0,
            1, 1.0f, 0);

        ln4_k<<<NROWS/8, 256>>>(part, bol, xin, s1l, o1l, x, xh);

        // MLP1: [4096,256]x[256,1024] ReLU
        gemm_h<true><<<dim3(Mc/128, NROWS/128, 1), 256, SMH_T>>>(
            xh, w1, nullptr, hh, b1l, Dc, Dc, Mc, Mc,
            0,0,0,0,0,0,0, 1, 1.0f, 2);

        // MLP2 split-K=4
        gemm_h<true><<<dim3(Dc/128, NROWS/128, 4), 256, SMH_T>>>(
            hh, w2, part, nullptr, nullptr, 256, Mc, Dc, Dc,
            256L, 0, 256L*Dc, 0, (long)NROWS*Dc, 0, 0,
            1, 1.0f, 0);

        float* lnout = (l == Lc - 1) ? (float*)d_out : x;
        ln4_k<<<NROWS/8, 256>>>(part, b2l, x, s2l, o2l, lnout, xh);

        xin = x;
    }
}

// round 12
// speedup vs baseline: 1.2564x; 1.0034x over previous
#include <cuda_runtime.h>
#include <cuda_fp16.h>
#include <cstdint>
#include <math.h>

// Problem constants
#define Lc 2
#define Bc 4
#define Tc 1024
#define Dc 256
#define Hc 4
#define Mc 1024
#define NROWS (Bc*Tc)      // 4096
#define HD (Hc*Dc)         // 1024
#define LN_EPS 1e-5f

// ---------------------------------------------------------------------------
// Scratch (device globals; allocation-free contract)
// ---------------------------------------------------------------------------
__device__ float  g_x[NROWS*Dc];
__device__ float  g_part[4L*NROWS*Dc];         // split-K partials (16MB)
__device__ float  g_s[(long)Bc*Hc*Tc*Tc];      // fp32 attention scores (64MB)
__device__ float  g_bqkv[Lc*3*HD];             // packed QKV biases
__device__ __half g_xh[NROWS*Dc];
__device__ __half g_qkvh[3L*NROWS*HD];         // q | k | v contiguous
__device__ __half g_aoh[NROWS*HD];
__device__ __half g_hh[NROWS*Mc];
__device__ __half g_ph[(long)Bc*Hc*Tc*Tc];     // half probs (32MB)
__device__ __half g_wqkvh[Lc*3*Dc*HD];         // [l][q,k,v][D*HD]
__device__ __half g_woh[Lc*HD*Dc];
__device__ __half g_w1h[Lc*Dc*Mc];
__device__ __half g_w2h[Lc*Mc*Dc];

// ---------------------------------------------------------------------------
// Helpers
// ---------------------------------------------------------------------------
__device__ __forceinline__ uint32_t smem_u32(const void* p) {
    uint32_t a;
    asm("{ .reg .u64 t; cvta.to.shared.u64 t, %1; cvt.u32.u64 %0, t; }"
        : "=r"(a) : "l"(p));
    return a;
}
__device__ __forceinline__ void cp16(uint32_t dst, const void* src) {
    asm volatile("cp.async.cg.shared.global [%0], [%1], 16;"
                 :: "r"(dst), "l"(src) : "memory");
}
#define CP_COMMIT() asm volatile("cp.async.commit_group;" ::: "memory")
#define CP_WAIT(n)  asm volatile("cp.async.wait_group %0;" :: "n"(n) : "memory")

#define LDSM4(r, addr) \
    asm volatile("ldmatrix.sync.aligned.m8n8.x4.shared.b16 {%0,%1,%2,%3}, [%4];" \
        : "=r"((r)[0]), "=r"((r)[1]), "=r"((r)[2]), "=r"((r)[3]) : "r"(addr))
#define LDSM4T(r, addr) \
    asm volatile("ldmatrix.sync.aligned.m8n8.x4.trans.shared.b16 {%0,%1,%2,%3}, [%4];" \
        : "=r"((r)[0]), "=r"((r)[1]), "=r"((r)[2]), "=r"((r)[3]) : "r"(addr))

__device__ __forceinline__ void mma_f16(float* c, const uint32_t* a,
                                        uint32_t b0, uint32_t b1) {
    asm volatile(
        "mma.sync.aligned.m16n8k16.row.col.f32.f16.f16.f32 "
        "{%0,%1,%2,%3}, {%4,%5,%6,%7}, {%8,%9}, {%0,%1,%2,%3};"
        : "+f"(c[0]), "+f"(c[1]), "+f"(c[2]), "+f"(c[3])
        : "r"(a[0]), "r"(a[1]), "r"(a[2]), "r"(a[3]), "r"(b0), "r"(b1));
}

// ---------------------------------------------------------------------------
// Big-tile fp16 mma GEMM, BK=64, 3-stage cp.async ring, ONE barrier/chunk.
// 128x128 CTA tile, 8 warps.
//   TB=false: B is [N,K] K-major -> ldmatrix
//   TB=true : B is [K,N] N-major -> ldmatrix.trans
// flags bit1 = ReLU. Cf (fp32) / Ch (half), either may be null.
// blockIdx.z: z = zq*zdiv + zr; split-K via K-advancing strides + sC1 slabs.
// ---------------------------------------------------------------------------
template<bool TB>
__global__ void __launch_bounds__(256, 2) gemm_h(
    const __half* __restrict__ A, const __half* __restrict__ B,
    float* __restrict__ Cf, __half* __restrict__ Ch, const float* __restrict__ bias,
    int K, int lda, int ldb, int ldc,
    long sA1, long sA2, long sB1, long sB2, long sC1, long sC2, long sBias,
    int zdiv, float alpha, int flags)
{
    constexpr int ASZ = 128 * 144;                    // 18432
    constexpr int BSZ2 = TB ? 64 * 272 : 128 * 144;
    constexpr int STG = ASZ + BSZ2;

    extern __shared__ char smem[];
    uint32_t sbase = smem_u32(smem);

    int z  = blockIdx.z;
    int zq = z / zdiv, zr = z % zdiv;
    A  += (long)zq * sA1 + (long)zr * sA2;
    B  += (long)zq * sB1 + (long)zr * sB2;
    if (Cf)   Cf   += (long)zq * sC1 + (long)zr * sC2;
    if (Ch)   Ch   += (long)zq * sC1 + (long)zr * sC2;
    if (bias) bias += (long)zq * sBias;

    int t    = threadIdx.x;
    int lane = t & 31, w = t >> 5;
    int rowBase = blockIdx.y * 128;
    int colBase = blockIdx.x * 128;

    const __half* pA0 = A + (long)(rowBase + (t >> 3)) * lda + (t & 7) * 8;
    uint32_t sa0 = (uint32_t)((t >> 3) * 144 + (t & 7) * 16);
    const __half* pB0;
    uint32_t sb0;
    if (TB) {
        pB0 = B + (long)(t >> 4) * ldb + colBase + (t & 15) * 8;
        sb0 = (uint32_t)((t >> 4) * 272 + (t & 15) * 16);
    } else {
        pB0 = B + (long)(colBase + (t >> 3)) * ldb + (t & 7) * 8;
        sb0 = (uint32_t)((t >> 3) * 144 + (t & 7) * 16);
    }
    const long bChunk = TB ? 64L * ldb : 64L;
    const long bStepG = TB ? 16L * ldb : 32L * ldb;
    const uint32_t bStepS = TB ? 16u * 272 : 32u * 144;

    int NC = K >> 6;

    // prologue: chunks 0,1 -> stages 0,1 (two groups in flight)
    {
        #pragma unroll
        for (int i = 0; i < 4; i++) {
            cp16(sbase + sa0 + i * (32u * 144), pA0 + (long)i * 32 * lda);
            cp16(sbase + ASZ + sb0 + i * bStepS, pB0 + (long)i * bStepG);
        }
        CP_COMMIT();
    }
    if (NC > 1) {
        uint32_t base = sbase + STG;
        #pragma unroll
        for (int i = 0; i < 4; i++) {
            cp16(base + sa0 + i * (32u * 144), pA0 + 64 + (long)i * 32 * lda);
            cp16(base + ASZ + sb0 + i * bStepS, pB0 + bChunk + (long)i * bStepG);
        }
        CP_COMMIT();
    }

    int mb = (w & 3) * 32, nb = (w >> 2) * 64;
    int g  = lane >> 3, lr = lane & 7;
    int qr = lane >> 2, cl = lane & 3;

    float acc[2][8][4];
    #pragma unroll
    for (int i = 0; i < 2; i++)
        #pragma unroll
        for (int j = 0; j < 8; j++)
            #pragma unroll
            for (int u = 0; u < 4; u++) acc[i][j][u] = 0.0f;

    int st = 0;   // stage of chunk c
    int ld = 2;   // stage for chunk c+2 (vacated by chunk c-1)
    for (int c = 0; c < NC; c++) {
        if (c + 1 < NC) { CP_WAIT(1); } else { CP_WAIT(0); }
        __syncthreads();   // chunk c resident; all warps finished chunk c-1

        if (c + 2 < NC) {
            uint32_t base = sbase + ld * STG;
            const __half* pAc = pA0 + (c + 2) * 64;
            const __half* pBc = pB0 + (c + 2) * bChunk;
            #pragma unroll
            for (int i = 0; i < 4; i++) {
                cp16(base + sa0 + i * (32u * 144), pAc + (long)i * 32 * lda);
                cp16(base + ASZ + sb0 + i * bStepS, pBc + (long)i * bStepG);
            }
            CP_COMMIT();
        }

        uint32_t As = sbase + st * STG;
        uint32_t Bs = As + ASZ;

        #pragma unroll
        for (int kk = 0; kk < 64; kk += 16) {
            uint32_t af[2][4];
            #pragma unroll
            for (int mt = 0; mt < 2; mt++) {
                uint32_t addr = As + (uint32_t)((mb + mt * 16 + (g & 1) * 8 + lr) * 144
                                                + ((g >> 1) * 8 + kk) * 2);
                LDSM4(af[mt], addr);
            }
            #pragma unroll
            for (int np = 0; np < 4; np++) {
                uint32_t bf[4];
                if (TB) {
                    uint32_t addr = Bs + (uint32_t)((kk + (g & 1) * 8 + lr) * 272
                                                    + (nb + np * 16 + (g >> 1) * 8) * 2);
                    LDSM4T(bf, addr);
                } else {
                    uint32_t addr = Bs + (uint32_t)((nb + np * 16 + (g >> 1) * 8 + lr) * 144
                                                    + ((g & 1) * 8 + kk) * 2);
                    LDSM4(bf, addr);
                }
                mma_f16(acc[0][np * 2 + 0], af[0], bf[0], bf[1]);
                mma_f16(acc[0][np * 2 + 1], af[0], bf[2], bf[3]);
                mma_f16(acc[1][np * 2 + 0], af[1], bf[0], bf[1]);
                mma_f16(acc[1][np * 2 + 1], af[1], bf[2], bf[3]);
            }
        }
        st = (st == 2) ? 0 : st + 1;
        ld = (ld == 2) ? 0 : ld + 1;
    }

    #pragma unroll
    for (int mt = 0; mt < 2; mt++) {
        int r0 = rowBase + mb + mt * 16 + qr;
        #pragma unroll
        for (int nt = 0; nt < 8; nt++) {
            int c0 = colBase + nb + nt * 8 + cl * 2;
            float b0 = 0.0f, b1 = 0.0f;
            if (bias) { b0 = bias[c0]; b1 = bias[c0 + 1]; }
            float v0 = (acc[mt][nt][0] + b0) * alpha;
            float v1 = (acc[mt][nt][1] + b1) * alpha;
            float v2 = (acc[mt][nt][2] + b0) * alpha;
            float v3 = (acc[mt][nt][3] + b1) * alpha;
            if (flags & 2) {
                v0 = fmaxf(v0, 0.0f); v1 = fmaxf(v1, 0.0f);
                v2 = fmaxf(v2, 0.0f); v3 = fmaxf(v3, 0.0f);
            }
            if (Cf) {
                *(float2*)&Cf[(long)r0 * ldc + c0]       = make_float2(v0, v1);
                *(float2*)&Cf[(long)(r0 + 8) * ldc + c0] = make_float2(v2, v3);
            }
            if (Ch) {
                *(__half2*)&Ch[(long)r0 * ldc + c0]       = __floats2half2_rn(v0, v1);
                *(__half2*)&Ch[(long)(r0 + 8) * ldc + c0] = __floats2half2_rn(v2, v3);
            }
        }
    }
}

// ---------------------------------------------------------------------------
// One-shot convert/pack kernel (Round-6 layout).
// ---------------------------------------------------------------------------
__global__ void __launch_bounds__(256) cvt_all_k(
    const float* __restrict__ qf,
    const float* __restrict__ Wq, const float* __restrict__ Wk,
    const float* __restrict__ Wv, const float* __restrict__ Wo,
    const float* __restrict__ W1, const float* __restrict__ W2,
    const float* __restrict__ bq, const float* __restrict__ bk,
    const float* __restrict__ bv)
{
    int b = blockIdx.x;
    int tid = threadIdx.x;

    if (b >= 4096) {
        int j = b - 4096;
        int l = j / 3, tt = j % 3;
        const float* src = (tt == 0 ? bq : tt == 1 ? bk : bv) + (long)l * HD;
        float* dst = g_bqkv + (long)(l * 3 + tt) * HD;
        *(float4*)&dst[tid * 4] = *(const float4*)&src[tid * 4];
        return;
    }

    const float* src; __half* dst; long off;
    if (b < 1024) {
        src = qf; dst = g_xh; off = (long)b * 1024;
    } else if (b < 2560) {
        int i = b - 1024;
        int j = i >> 8;
        int r = i & 255;
        int l = j / 3, tt = j % 3;
        src = (tt == 0 ? Wq : tt == 1 ? Wk : Wv) + (long)l * Dc * HD;
        dst = g_wqkvh + (long)j * Dc * HD;
        off = (long)r * 1024;
    } else if (b < 3072) {
        src = Wo; dst = g_woh; off = (long)(b - 2560) * 1024;
    } else if (b < 3584) {
        src = W1; dst = g_w1h; off = (long)(b - 3072) * 1024;
    } else {
        src = W2; dst = g_w2h; off = (long)(b - 3584) * 1024;
    }
    long idx = off + tid * 4;
    float4 v = *(const float4*)&src[idx];
    *(__half2*)&dst[idx]     = __floats2half2_rn(v.x, v.y);
    *(__half2*)&dst[idx + 2] = __floats2half2_rn(v.z, v.w);
}

// ---------------------------------------------------------------------------
// Warp-per-row softmax: fp32 scores -> half probs. Row = Tc = 1024.
// ---------------------------------------------------------------------------
__global__ void __launch_bounds__(256) softmax_k(const float* __restrict__ S,
                                                 __half* __restrict__ P)
{
    long wrow = (long)blockIdx.x * 8 + (threadIdx.x >> 5);
    int  l    = threadIdx.x & 31;
    const float* row = S + wrow * Tc;
    __half* prow = P + wrow * Tc;

    float4 v[8];
    #pragma unroll
    for (int j = 0; j < 8; j++)
        v[j] = *(const float4*)&row[j * 128 + l * 4];

    float m = -1e30f;
    #pragma unroll
    for (int j = 0; j < 8; j++)
        m = fmaxf(m, fmaxf(fmaxf(v[j].x, v[j].y), fmaxf(v[j].z, v[j].w)));
    #pragma unroll
    for (int o = 16; o > 0; o >>= 1)
        m = fmaxf(m, __shfl_xor_sync(0xffffffffu, m, o));

    float s = 0.0f;
    #pragma unroll
    for (int j = 0; j < 8; j++) {
        v[j].x = __expf(v[j].x - m); v[j].y = __expf(v[j].y - m);
        v[j].z = __expf(v[j].z - m); v[j].w = __expf(v[j].w - m);
        s += (v[j].x + v[j].y) + (v[j].z + v[j].w);
    }
    #pragma unroll
    for (int o = 16; o > 0; o >>= 1)
        s += __shfl_xor_sync(0xffffffffu, s, o);

    float inv = 1.0f / s;
    #pragma unroll
    for (int j = 0; j < 8; j++) {
        *(__half2*)&prow[j * 128 + l * 4]     = __floats2half2_rn(v[j].x * inv, v[j].y * inv);
        *(__half2*)&prow[j * 128 + l * 4 + 2] = __floats2half2_rn(v[j].z * inv, v[j].w * inv);
    }
}

// ---------------------------------------------------------------------------
// Warp-per-row fused residual + LayerNorm (D=256), dual fp32 + fp16 output.
// ---------------------------------------------------------------------------
__global__ void __launch_bounds__(256) ln_k(
    const float* __restrict__ a, const float* __restrict__ res,
    const float* __restrict__ sg, const float* __restrict__ bg,
    float* __restrict__ outF, __half* __restrict__ outH)
{
    long wrow = (long)blockIdx.x * 8 + (threadIdx.x >> 5);
    int  l    = threadIdx.x & 31;
    long base = wrow * Dc;

    float4 v[2];
    #pragma unroll
    for (int j = 0; j < 2; j++) {
        float4 av = *(const float4*)&a[base + j * 128 + l * 4];
        float4 rv = *(const float4*)&res[base + j * 128 + l * 4];
        v[j] = make_float4(av.x + rv.x, av.y + rv.y, av.z + rv.z, av.w + rv.w);
    }

    float s = (v[0].x + v[0].y + v[0].z + v[0].w)
            + (v[1].x + v[1].y + v[1].z + v[1].w);
    #pragma unroll
    for (int o = 16; o > 0; o >>= 1) s += __shfl_xor_sync(0xffffffffu, s, o);
    float mean = s * (1.0f / Dc);

    float q = 0.0f;
    #pragma unroll
    for (int j = 0; j < 2; j++) {
        float dx = v[j].x - mean, dy = v[j].y - mean;
        float dz = v[j].z - mean, dw = v[j].w - mean;
        q += dx*dx + dy*dy + dz*dz + dw*dw;
    }
    #pragma unroll
    for (int o = 16; o > 0; o >>= 1) q += __shfl_xor_sync(0xffffffffu, q, o);
    float rstd = rsqrtf(q * (1.0f / Dc) + LN_EPS);

    #pragma unroll
    for (int j = 0; j < 2; j++) {
        int c = j * 128 + l * 4;
        float o0 = (v[j].x - mean) * rstd * sg[c]     + bg[c];
        float o1 = (v[j].y - mean) * rstd * sg[c + 1] + bg[c + 1];
        float o2 = (v[j].z - mean) * rstd * sg[c + 2] + bg[c + 2];
        float o3 = (v[j].w - mean) * rstd * sg[c + 3] + bg[c + 3];
        *(float4*)&outF[base + c] = make_float4(o0, o1, o2, o3);
        *(__half2*)&outH[base + c]     = __floats2half2_rn(o0, o1);
        *(__half2*)&outH[base + c + 2] = __floats2half2_rn(o2, o3);
    }
}

// ---------------------------------------------------------------------------
// Warp-per-row split-K reduce (4 slabs) + bias + residual + LayerNorm.
// ---------------------------------------------------------------------------
__global__ void __launch_bounds__(256) ln4_k(
    const float* __restrict__ part, const float* __restrict__ bias,
    const float* __restrict__ res,
    const float* __restrict__ sg, const float* __restrict__ bg,
    float* __restrict__ outF, __half* __restrict__ outH)
{
    long wrow = (long)blockIdx.x * 8 + (threadIdx.x >> 5);
    int  l    = threadIdx.x & 31;
    long base = wrow * Dc;
    const long SS = (long)NROWS * Dc;

    float4 v[2];
    #pragma unroll
    for (int j = 0; j < 2; j++) {
        long i = base + j * 128 + l * 4;
        float4 p0 = *(const float4*)&part[i];
        float4 p1 = *(const float4*)&part[i + SS];
        float4 p2 = *(const float4*)&part[i + 2*SS];
        float4 p3 = *(const float4*)&part[i + 3*SS];
        float4 rv = *(const float4*)&res[i];
        int c = j * 128 + l * 4;
        v[j] = make_float4(p0.x + p1.x + p2.x + p3.x + bias[c]     + rv.x,
                           p0.y + p1.y + p2.y + p3.y + bias[c + 1] + rv.y,
                           p0.z + p1.z + p2.z + p3.z + bias[c + 2] + rv.z,
                           p0.w + p1.w + p2.w + p3.w + bias[c + 3] + rv.w);
    }

    float s = (v[0].x + v[0].y + v[0].z + v[0].w)
            + (v[1].x + v[1].y + v[1].z + v[1].w);
    #pragma unroll
    for (int o = 16; o > 0; o >>= 1) s += __shfl_xor_sync(0xffffffffu, s, o);
    float mean = s * (1.0f / Dc);

    float q = 0.0f;
    #pragma unroll
    for (int j = 0; j < 2; j++) {
        float dx = v[j].x - mean, dy = v[j].y - mean;
        float dz = v[j].z - mean, dw = v[j].w - mean;
        q += dx*dx + dy*dy + dz*dz + dw*dw;
    }
    #pragma unroll
    for (int o = 16; o > 0; o >>= 1) q += __shfl_xor_sync(0xffffffffu, q, o);
    float rstd = rsqrtf(q * (1.0f / Dc) + LN_EPS);

    #pragma unroll
    for (int j = 0; j < 2; j++) {
        int c = j * 128 + l * 4;
        float o0 = (v[j].x - mean) * rstd * sg[c]     + bg[c];
        float o1 = (v[j].y - mean) * rstd * sg[c + 1] + bg[c + 1];
        float o2 = (v[j].z - mean) * rstd * sg[c + 2] + bg[c + 2];
        float o3 = (v[j].w - mean) * rstd * sg[c + 3] + bg[c + 3];
        *(float4*)&outF[base + c] = make_float4(o0, o1, o2, o3);
        *(__half2*)&outH[base + c]     = __floats2half2_rn(o0, o1);
        *(__half2*)&outH[base + c + 2] = __floats2half2_rn(o2, o3);
    }
}

// ---------------------------------------------------------------------------
// Launch
// ---------------------------------------------------------------------------
extern "C" void kernel_launch(void* const* d_in, const int* in_sizes, int n_in,
                              void* d_out, int out_size)
{
    const float* queries = (const float*)d_in[0];
    const float* Wq   = (const float*)d_in[1];
    const float* bq   = (const float*)d_in[2];
    const float* Wk   = (const float*)d_in[3];
    const float* bk   = (const float*)d_in[4];
    const float* Wv   = (const float*)d_in[5];
    const float* bv   = (const float*)d_in[6];
    const float* Wo   = (const float*)d_in[7];
    const float* bo   = (const float*)d_in[8];
    const float* ln1s = (const float*)d_in[9];
    const float* ln1b = (const float*)d_in[10];
    const float* W1   = (const float*)d_in[11];
    const float* b1   = (const float*)d_in[12];
    const float* W2   = (const float*)d_in[13];
    const float* b2   = (const float*)d_in[14];
    const float* ln2s = (const float*)d_in[15];
    const float* ln2b = (const float*)d_in[16];

    float *x, *part, *sc, *bqkv;
    __half *xh, *qkvh, *aoh, *hh, *ph;
    __half *wqkvh, *woh, *w1h, *w2h;
    cudaGetSymbolAddress((void**)&x,     g_x);
    cudaGetSymbolAddress((void**)&part,  g_part);
    cudaGetSymbolAddress((void**)&sc,    g_s);
    cudaGetSymbolAddress((void**)&bqkv,  g_bqkv);
    cudaGetSymbolAddress((void**)&xh,    g_xh);
    cudaGetSymbolAddress((void**)&qkvh,  g_qkvh);
    cudaGetSymbolAddress((void**)&aoh,   g_aoh);
    cudaGetSymbolAddress((void**)&hh,    g_hh);
    cudaGetSymbolAddress((void**)&ph,    g_ph);
    cudaGetSymbolAddress((void**)&wqkvh, g_wqkvh);
    cudaGetSymbolAddress((void**)&woh,   g_woh);
    cudaGetSymbolAddress((void**)&w1h,   g_w1h);
    cudaGetSymbolAddress((void**)&w2h,   g_w2h);

    const int SMH_T = 3 * (128*144 + 64*272);   // 107520
    const int SMH_F = 3 * (128*144 + 128*144);  // 110592
    cudaFuncSetAttribute(gemm_h<true>,  cudaFuncAttributeMaxDynamicSharedMemorySize, SMH_T);
    cudaFuncSetAttribute(gemm_h<false>, cudaFuncAttributeMaxDynamicSharedMemorySize, SMH_F);

    const float* xin = queries;
    const float qscale = 1.0f / 16.0f;

    cvt_all_k<<<4102, 256>>>(queries, Wq, Wk, Wv, Wo, W1, W2, bq, bk, bv);

    __half* qh = qkvh;
    __half* kh = qkvh + (long)NROWS * HD;
    __half* vh = qkvh + 2L * NROWS * HD;

    for (int l = 0; l < Lc; l++) {
        const __half* wqkv = wqkvh + (long)l * 3 * Dc * HD;
        const __half* w1 = w1h + (long)l * Dc * Mc;
        const __half* w2 = w2h + (long)l * Mc * Dc;
        const __half* wo = woh + (long)l * HD * Dc;
        const float* bql3 = bqkv + (long)l * 3 * HD;
        const float* bol = bo + (long)l * Dc;
        const float* b1l = b1 + (long)l * Mc;
        const float* b2l = b2 + (long)l * Dc;
        const float* s1l = ln1s + (long)l * Dc;
        const float* o1l = ln1b + (long)l * Dc;
        const float* s2l = ln2s + (long)l * Dc;
        const float* o2l = ln2b + (long)l * Dc;

        // Fused QKV (768 CTAs, K=256)
        gemm_h<true><<<dim3(HD/128, NROWS/128, 3), 256, SMH_T>>>(
            xh, wqkv, nullptr, qkvh, bql3, Dc, Dc, HD, HD,
            0, 0, (long)Dc*HD, 0, (long)NROWS*HD, 0, (long)HD,
            1, 1.0f, 0);

        // scores = (q @ k^T) * qscale  (1024 CTAs, K=256)
        gemm_h<false><<<dim3(Tc/128, Tc/128, Bc*Hc), 256, SMH_F>>>(
            qh, kh, sc, nullptr, nullptr, Dc, HD, HD, Tc,
            (long)Tc*HD, (long)Dc,
            (long)Tc*HD, (long)Dc,
            (long)Hc*Tc*Tc, (long)Tc*Tc, 0,
            Hc, qscale, 0);

        softmax_k<<<Bc*Hc*Tc/8, 256>>>(sc, ph);

        // PV: probs @ V  (256 CTAs, K=1024)
        gemm_h<true><<<dim3(Dc/128, Tc/128, Bc*Hc), 256, SMH_T>>>(
            ph, vh, nullptr, aoh, nullptr, Tc, Tc, HD, HD,
            (long)Hc*Tc*Tc, (long)Tc*Tc,
            (long)Tc*HD, (long)Dc,
            (long)Tc*HD, (long)Dc, 0,
            Hc, 1.0f, 0);

        // Wo split-K=4
        gemm_h<true><<<dim3(Dc/128, NROWS/128, 4), 256, SMH_T>>>(
            aoh, wo, part, nullptr, nullptr, 256, HD, Dc, Dc,
            256L, 0, 256L*Dc, 0, (long)NROWS*Dc, 0, 0,
            1, 1.0f, 0);

        ln4_k<<<NROWS/8, 256>>>(part, bol, xin, s1l, o1l, x, xh);

        // MLP1: [4096,256]x[256,1024] ReLU
        gemm_h<true><<<dim3(Mc/128, NROWS/128, 1), 256, SMH_T>>>(
            xh, w1, nullptr, hh, b1l, Dc, Dc, Mc, Mc,
            0,0,0,0,0,0,0, 1, 1.0f, 2);

        // MLP2 split-K=4
        gemm_h<true><<<dim3(Dc/128, NROWS/128, 4), 256, SMH_T>>>(
            hh, w2, part, nullptr, nullptr, 256, Mc, Dc, Dc,
            256L, 0, 256L*Dc, 0, (long)NROWS*Dc, 0, 0,
            1, 1.0f, 0);

        float* lnout = (l == Lc - 1) ? (float*)d_out : x;
        ln4_k<<<NROWS/8, 256>>>(part, b2l, x, s2l, o2l, lnout, xh);

        xin = x;
    }
}

// round 13
// speedup vs baseline: 1.3814x; 1.0996x over previous
#include <cuda_runtime.h>
#include <cuda_fp16.h>
#include <cstdint>
#include <math.h>

// Problem constants
#define Lc 2
#define Bc 4
#define Tc 1024
#define Dc 256
#define Hc 4
#define Mc 1024
#define NROWS (Bc*Tc)      // 4096
#define HD (Hc*Dc)         // 1024
#define LN_EPS 1e-5f

// ---------------------------------------------------------------------------
// Scratch (device globals; allocation-free contract)
// ---------------------------------------------------------------------------
__device__ float  g_x[NROWS*Dc];
__device__ float  g_part[4L*NROWS*Dc];         // split-K partials (16MB)
__device__ float  g_bqkv[Lc*3*HD];             // packed QKV biases
__device__ __half g_xh[NROWS*Dc];
__device__ __half g_qkvh[3L*NROWS*HD];         // q | k | v contiguous
__device__ __half g_aoh[NROWS*HD];
__device__ __half g_hh[NROWS*Mc];
__device__ __half g_wqkvh[Lc*3*Dc*HD];         // [l][q,k,v][D*HD]
__device__ __half g_woh[Lc*HD*Dc];
__device__ __half g_w1h[Lc*Dc*Mc];
__device__ __half g_w2h[Lc*Mc*Dc];

// ---------------------------------------------------------------------------
// Helpers
// ---------------------------------------------------------------------------
__device__ __forceinline__ uint32_t smem_u32(const void* p) {
    uint32_t a;
    asm("{ .reg .u64 t; cvta.to.shared.u64 t, %1; cvt.u32.u64 %0, t; }"
        : "=r"(a) : "l"(p));
    return a;
}
__device__ __forceinline__ void cp16(uint32_t dst, const void* src) {
    asm volatile("cp.async.cg.shared.global [%0], [%1], 16;"
                 :: "r"(dst), "l"(src) : "memory");
}
#define CP_COMMIT() asm volatile("cp.async.commit_group;" ::: "memory")
#define CP_WAIT(n)  asm volatile("cp.async.wait_group %0;" :: "n"(n) : "memory")

#define LDSM4(r, addr) \
    asm volatile("ldmatrix.sync.aligned.m8n8.x4.shared.b16 {%0,%1,%2,%3}, [%4];" \
        : "=r"((r)[0]), "=r"((r)[1]), "=r"((r)[2]), "=r"((r)[3]) : "r"(addr))
#define LDSM4T(r, addr) \
    asm volatile("ldmatrix.sync.aligned.m8n8.x4.trans.shared.b16 {%0,%1,%2,%3}, [%4];" \
        : "=r"((r)[0]), "=r"((r)[1]), "=r"((r)[2]), "=r"((r)[3]) : "r"(addr))

__device__ __forceinline__ void mma_f16(float* c, const uint32_t* a,
                                        uint32_t b0, uint32_t b1) {
    asm volatile(
        "mma.sync.aligned.m16n8k16.row.col.f32.f16.f16.f32 "
        "{%0,%1,%2,%3}, {%4,%5,%6,%7}, {%8,%9}, {%0,%1,%2,%3};"
        : "+f"(c[0]), "+f"(c[1]), "+f"(c[2]), "+f"(c[3])
        : "r"(a[0]), "r"(a[1]), "r"(a[2]), "r"(a[3]), "r"(b0), "r"(b1));
}

// ---------------------------------------------------------------------------
// Big-tile fp16 mma GEMM, BK=64, 3-stage cp.async ring (Round-12 config).
// ---------------------------------------------------------------------------
template<bool TB>
__global__ void __launch_bounds__(256, 2) gemm_h(
    const __half* __restrict__ A, const __half* __restrict__ B,
    float* __restrict__ Cf, __half* __restrict__ Ch, const float* __restrict__ bias,
    int K, int lda, int ldb, int ldc,
    long sA1, long sA2, long sB1, long sB2, long sC1, long sC2, long sBias,
    int zdiv, float alpha, int flags)
{
    constexpr int ASZ = 128 * 144;
    constexpr int BSZ2 = TB ? 64 * 272 : 128 * 144;
    constexpr int STG = ASZ + BSZ2;

    extern __shared__ char smem[];
    uint32_t sbase = smem_u32(smem);

    int z  = blockIdx.z;
    int zq = z / zdiv, zr = z % zdiv;
    A  += (long)zq * sA1 + (long)zr * sA2;
    B  += (long)zq * sB1 + (long)zr * sB2;
    if (Cf)   Cf   += (long)zq * sC1 + (long)zr * sC2;
    if (Ch)   Ch   += (long)zq * sC1 + (long)zr * sC2;
    if (bias) bias += (long)zq * sBias;

    int t    = threadIdx.x;
    int lane = t & 31, w = t >> 5;
    int rowBase = blockIdx.y * 128;
    int colBase = blockIdx.x * 128;

    const __half* pA0 = A + (long)(rowBase + (t >> 3)) * lda + (t & 7) * 8;
    uint32_t sa0 = (uint32_t)((t >> 3) * 144 + (t & 7) * 16);
    const __half* pB0;
    uint32_t sb0;
    if (TB) {
        pB0 = B + (long)(t >> 4) * ldb + colBase + (t & 15) * 8;
        sb0 = (uint32_t)((t >> 4) * 272 + (t & 15) * 16);
    } else {
        pB0 = B + (long)(colBase + (t >> 3)) * ldb + (t & 7) * 8;
        sb0 = (uint32_t)((t >> 3) * 144 + (t & 7) * 16);
    }
    const long bChunk = TB ? 64L * ldb : 64L;
    const long bStepG = TB ? 16L * ldb : 32L * ldb;
    const uint32_t bStepS = TB ? 16u * 272 : 32u * 144;

    int NC = K >> 6;

    {
        #pragma unroll
        for (int i = 0; i < 4; i++) {
            cp16(sbase + sa0 + i * (32u * 144), pA0 + (long)i * 32 * lda);
            cp16(sbase + ASZ + sb0 + i * bStepS, pB0 + (long)i * bStepG);
        }
        CP_COMMIT();
    }
    if (NC > 1) {
        uint32_t base = sbase + STG;
        #pragma unroll
        for (int i = 0; i < 4; i++) {
            cp16(base + sa0 + i * (32u * 144), pA0 + 64 + (long)i * 32 * lda);
            cp16(base + ASZ + sb0 + i * bStepS, pB0 + bChunk + (long)i * bStepG);
        }
        CP_COMMIT();
    }

    int mb = (w & 3) * 32, nb = (w >> 2) * 64;
    int g  = lane >> 3, lr = lane & 7;
    int qr = lane >> 2, cl = lane & 3;

    float acc[2][8][4];
    #pragma unroll
    for (int i = 0; i < 2; i++)
        #pragma unroll
        for (int j = 0; j < 8; j++)
            #pragma unroll
            for (int u = 0; u < 4; u++) acc[i][j][u] = 0.0f;

    int st = 0, ld = 2;
    for (int c = 0; c < NC; c++) {
        if (c + 1 < NC) { CP_WAIT(1); } else { CP_WAIT(0); }
        __syncthreads();

        if (c + 2 < NC) {
            uint32_t base = sbase + ld * STG;
            const __half* pAc = pA0 + (c + 2) * 64;
            const __half* pBc = pB0 + (c + 2) * bChunk;
            #pragma unroll
            for (int i = 0; i < 4; i++) {
                cp16(base + sa0 + i * (32u * 144), pAc + (long)i * 32 * lda);
                cp16(base + ASZ + sb0 + i * bStepS, pBc + (long)i * bStepG);
            }
            CP_COMMIT();
        }

        uint32_t As = sbase + st * STG;
        uint32_t Bs = As + ASZ;

        #pragma unroll
        for (int kk = 0; kk < 64; kk += 16) {
            uint32_t af[2][4];
            #pragma unroll
            for (int mt = 0; mt < 2; mt++) {
                uint32_t addr = As + (uint32_t)((mb + mt * 16 + (g & 1) * 8 + lr) * 144
                                                + ((g >> 1) * 8 + kk) * 2);
                LDSM4(af[mt], addr);
            }
            #pragma unroll
            for (int np = 0; np < 4; np++) {
                uint32_t bf[4];
                if (TB) {
                    uint32_t addr = Bs + (uint32_t)((kk + (g & 1) * 8 + lr) * 272
                                                    + (nb + np * 16 + (g >> 1) * 8) * 2);
                    LDSM4T(bf, addr);
                } else {
                    uint32_t addr = Bs + (uint32_t)((nb + np * 16 + (g >> 1) * 8 + lr) * 144
                                                    + ((g & 1) * 8 + kk) * 2);
                    LDSM4(bf, addr);
                }
                mma_f16(acc[0][np * 2 + 0], af[0], bf[0], bf[1]);
                mma_f16(acc[0][np * 2 + 1], af[0], bf[2], bf[3]);
                mma_f16(acc[1][np * 2 + 0], af[1], bf[0], bf[1]);
                mma_f16(acc[1][np * 2 + 1], af[1], bf[2], bf[3]);
            }
        }
        st = (st == 2) ? 0 : st + 1;
        ld = (ld == 2) ? 0 : ld + 1;
    }

    #pragma unroll
    for (int mt = 0; mt < 2; mt++) {
        int r0 = rowBase + mb + mt * 16 + qr;
        #pragma unroll
        for (int nt = 0; nt < 8; nt++) {
            int c0 = colBase + nb + nt * 8 + cl * 2;
            float b0 = 0.0f, b1 = 0.0f;
            if (bias) { b0 = bias[c0]; b1 = bias[c0 + 1]; }
            float v0 = (acc[mt][nt][0] + b0) * alpha;
            float v1 = (acc[mt][nt][1] + b1) * alpha;
            float v2 = (acc[mt][nt][2] + b0) * alpha;
            float v3 = (acc[mt][nt][3] + b1) * alpha;
            if (flags & 2) {
                v0 = fmaxf(v0, 0.0f); v1 = fmaxf(v1, 0.0f);
                v2 = fmaxf(v2, 0.0f); v3 = fmaxf(v3, 0.0f);
            }
            if (Cf) {
                *(float2*)&Cf[(long)r0 * ldc + c0]       = make_float2(v0, v1);
                *(float2*)&Cf[(long)(r0 + 8) * ldc + c0] = make_float2(v2, v3);
            }
            if (Ch) {
                *(__half2*)&Ch[(long)r0 * ldc + c0]       = __floats2half2_rn(v0, v1);
                *(__half2*)&Ch[(long)(r0 + 8) * ldc + c0] = __floats2half2_rn(v2, v3);
            }
        }
    }
}

// ---------------------------------------------------------------------------
// Flash attention: out = softmax(Q K^T / 16) V   per (b,h), fused.
// Grid (8 q-tiles, 16 bh). 8 warps; warp owns 16 Q rows. KV tiles of 64 rows,
// double-buffered cp.async. S C-frags repack directly into P A-frags.
// SMEM: Q 128x528B + 2x(K 64x528B) + 2x(V 64x528B) = 198KB.
// ---------------------------------------------------------------------------
#define FA_QSZ (128*528)
#define FA_TSZ (64*528)
#define FA_SMEM (FA_QSZ + 4*FA_TSZ)   // 202752

__global__ void __launch_bounds__(256, 1) flash_k(
    const __half* __restrict__ Qg, const __half* __restrict__ Kg,
    const __half* __restrict__ Vg, __half* __restrict__ Og, float qscale)
{
    extern __shared__ char smem[];
    uint32_t sQ = smem_u32(smem);
    uint32_t sK = sQ + FA_QSZ;
    uint32_t sV = sK + 2*FA_TSZ;

    int qt = blockIdx.x;
    int bh = blockIdx.y;
    int b = bh >> 2, h = bh & 3;

    int t = threadIdx.x, lane = t & 31, w = t >> 5;
    int g = lane >> 3, lr = lane & 7;
    int qr = lane >> 2, cl = lane & 3;

    const __half* qp = Qg + ((long)b*Tc + qt*128)*HD + h*Dc;
    const __half* kp = Kg + (long)b*Tc*HD + h*Dc;
    const __half* vp = Vg + (long)b*Tc*HD + h*Dc;

    // Q load: 128 rows x 32 16B-units
    #pragma unroll
    for (int i = 0; i < 16; i++) {
        int idx = t + i*256;
        int row = idx >> 5, u = idx & 31;
        cp16(sQ + (uint32_t)(row*528 + u*16), qp + (long)row*HD + u*8);
    }
    CP_COMMIT();

    // KV tiles 0,1 -> stages 0,1
    #pragma unroll
    for (int p = 0; p < 2; p++) {
        #pragma unroll
        for (int i = 0; i < 8; i++) {
            int idx = t + i*256;
            int row = idx >> 5, u = idx & 31;
            cp16(sK + p*FA_TSZ + (uint32_t)(row*528 + u*16),
                 kp + (long)(p*64 + row)*HD + u*8);
            cp16(sV + p*FA_TSZ + (uint32_t)(row*528 + u*16),
                 vp + (long)(p*64 + row)*HD + u*8);
        }
        CP_COMMIT();
    }

    float oacc[32][4];
    #pragma unroll
    for (int nt = 0; nt < 32; nt++)
        #pragma unroll
        for (int u = 0; u < 4; u++) oacc[nt][u] = 0.0f;
    float m0 = -1e30f, m1 = -1e30f, l0 = 0.0f, l1 = 0.0f;

    // Precompute frag base offsets
    uint32_t qoff = (uint32_t)((w*16 + (g&1)*8 + lr)*528 + ((g>>1)*8)*2);

    for (int j = 0; j < 16; j++) {
        int st = j & 1;
        if (j + 1 < 16) { CP_WAIT(1); } else { CP_WAIT(0); }
        __syncthreads();

        uint32_t Ks = sK + st*FA_TSZ;
        uint32_t Vs = sV + st*FA_TSZ;

        // ---- S = Q K^T  (16 rows x 64 cols per warp)
        float sacc[8][4];
        #pragma unroll
        for (int nt = 0; nt < 8; nt++)
            #pragma unroll
            for (int u = 0; u < 4; u++) sacc[nt][u] = 0.0f;

        #pragma unroll
        for (int kk = 0; kk < 256; kk += 16) {
            uint32_t af[4];
            LDSM4(af, sQ + qoff + (uint32_t)(kk*2));
            #pragma unroll
            for (int np = 0; np < 4; np++) {
                uint32_t bf[4];
                LDSM4(bf, Ks + (uint32_t)((np*16 + (g>>1)*8 + lr)*528 + ((g&1)*8 + kk)*2));
                mma_f16(sacc[np*2],   af, bf[0], bf[1]);
                mma_f16(sacc[np*2+1], af, bf[2], bf[3]);
            }
        }

        // ---- online softmax (rows qr and qr+8, quad-local)
        float tm0 = -1e30f, tm1 = -1e30f;
        #pragma unroll
        for (int nt = 0; nt < 8; nt++) {
            tm0 = fmaxf(tm0, fmaxf(sacc[nt][0], sacc[nt][1]));
            tm1 = fmaxf(tm1, fmaxf(sacc[nt][2], sacc[nt][3]));
        }
        tm0 = fmaxf(tm0, __shfl_xor_sync(0xffffffffu, tm0, 1));
        tm0 = fmaxf(tm0, __shfl_xor_sync(0xffffffffu, tm0, 2));
        tm1 = fmaxf(tm1, __shfl_xor_sync(0xffffffffu, tm1, 1));
        tm1 = fmaxf(tm1, __shfl_xor_sync(0xffffffffu, tm1, 2));
        tm0 *= qscale; tm1 *= qscale;

        float mn0 = fmaxf(m0, tm0), mn1 = fmaxf(m1, tm1);
        float r0 = __expf(m0 - mn0), r1 = __expf(m1 - mn1);

        #pragma unroll
        for (int nt = 0; nt < 32; nt++) {
            oacc[nt][0] *= r0; oacc[nt][1] *= r0;
            oacc[nt][2] *= r1; oacc[nt][3] *= r1;
        }

        float ps0 = 0.0f, ps1 = 0.0f;
        uint32_t pf[8][2];
        #pragma unroll
        for (int nt = 0; nt < 8; nt++) {
            float p0 = __expf(sacc[nt][0]*qscale - mn0);
            float p1 = __expf(sacc[nt][1]*qscale - mn0);
            float p2 = __expf(sacc[nt][2]*qscale - mn1);
            float p3 = __expf(sacc[nt][3]*qscale - mn1);
            ps0 += p0 + p1; ps1 += p2 + p3;
            __half2 h01 = __floats2half2_rn(p0, p1);
            __half2 h23 = __floats2half2_rn(p2, p3);
            pf[nt][0] = *(uint32_t*)&h01;
            pf[nt][1] = *(uint32_t*)&h23;
        }
        ps0 += __shfl_xor_sync(0xffffffffu, ps0, 1);
        ps0 += __shfl_xor_sync(0xffffffffu, ps0, 2);
        ps1 += __shfl_xor_sync(0xffffffffu, ps1, 1);
        ps1 += __shfl_xor_sync(0xffffffffu, ps1, 2);
        l0 = l0*r0 + ps0; l1 = l1*r1 + ps1;
        m0 = mn0; m1 = mn1;

        // ---- O += P V   (P A-frags direct from S C-frags)
        #pragma unroll
        for (int ks = 0; ks < 4; ks++) {
            uint32_t af[4] = { pf[2*ks][0], pf[2*ks][1], pf[2*ks+1][0], pf[2*ks+1][1] };
            #pragma unroll
            for (int np = 0; np < 16; np++) {
                uint32_t bf[4];
                LDSM4T(bf, Vs + (uint32_t)((ks*16 + (g&1)*8 + lr)*528
                                           + (np*16 + (g>>1)*8)*2));
                mma_f16(oacc[np*2],   af, bf[0], bf[1]);
                mma_f16(oacc[np*2+1], af, bf[2], bf[3]);
            }
        }

        __syncthreads();   // all warps done with stage st

        if (j + 2 < 16) {
            #pragma unroll
            for (int i = 0; i < 8; i++) {
                int idx = t + i*256;
                int row = idx >> 5, u = idx & 31;
                cp16(sK + st*FA_TSZ + (uint32_t)(row*528 + u*16),
                     kp + (long)((j+2)*64 + row)*HD + u*8);
                cp16(sV + st*FA_TSZ + (uint32_t)(row*528 + u*16),
                     vp + (long)((j+2)*64 + row)*HD + u*8);
            }
            CP_COMMIT();
        }
    }

    // ---- epilogue: normalize and store
    float i0 = 1.0f / l0, i1 = 1.0f / l1;
    long r0g = (long)b*Tc + qt*128 + w*16 + qr;
    __half* o0 = Og + r0g*HD + h*Dc;
    __half* o1 = o0 + 8L*HD;
    #pragma unroll
    for (int nt = 0; nt < 32; nt++) {
        *(__half2*)&o0[nt*8 + cl*2] = __floats2half2_rn(oacc[nt][0]*i0, oacc[nt][1]*i0);
        *(__half2*)&o1[nt*8 + cl*2] = __floats2half2_rn(oacc[nt][2]*i1, oacc[nt][3]*i1);
    }
}

// ---------------------------------------------------------------------------
// One-shot convert/pack kernel (Round-6 layout).
// ---------------------------------------------------------------------------
__global__ void __launch_bounds__(256) cvt_all_k(
    const float* __restrict__ qf,
    const float* __restrict__ Wq, const float* __restrict__ Wk,
    const float* __restrict__ Wv, const float* __restrict__ Wo,
    const float* __restrict__ W1, const float* __restrict__ W2,
    const float* __restrict__ bq, const float* __restrict__ bk,
    const float* __restrict__ bv)
{
    int b = blockIdx.x;
    int tid = threadIdx.x;

    if (b >= 4096) {
        int j = b - 4096;
        int l = j / 3, tt = j % 3;
        const float* src = (tt == 0 ? bq : tt == 1 ? bk : bv) + (long)l * HD;
        float* dst = g_bqkv + (long)(l * 3 + tt) * HD;
        *(float4*)&dst[tid * 4] = *(const float4*)&src[tid * 4];
        return;
    }

    const float* src; __half* dst; long off;
    if (b < 1024) {
        src = qf; dst = g_xh; off = (long)b * 1024;
    } else if (b < 2560) {
        int i = b - 1024;
        int j = i >> 8;
        int r = i & 255;
        int l = j / 3, tt = j % 3;
        src = (tt == 0 ? Wq : tt == 1 ? Wk : Wv) + (long)l * Dc * HD;
        dst = g_wqkvh + (long)j * Dc * HD;
        off = (long)r * 1024;
    } else if (b < 3072) {
        src = Wo; dst = g_woh; off = (long)(b - 2560) * 1024;
    } else if (b < 3584) {
        src = W1; dst = g_w1h; off = (long)(b - 3072) * 1024;
    } else {
        src = W2; dst = g_w2h; off = (long)(b - 3584) * 1024;
    }
    long idx = off + tid * 4;
    float4 v = *(const float4*)&src[idx];
    *(__half2*)&dst[idx]     = __floats2half2_rn(v.x, v.y);
    *(__half2*)&dst[idx + 2] = __floats2half2_rn(v.z, v.w);
}

// ---------------------------------------------------------------------------
// Warp-per-row fused residual + LayerNorm (D=256), dual fp32 + fp16 output.
// ---------------------------------------------------------------------------
__global__ void __launch_bounds__(256) ln_k(
    const float* __restrict__ a, const float* __restrict__ res,
    const float* __restrict__ sg, const float* __restrict__ bg,
    float* __restrict__ outF, __half* __restrict__ outH)
{
    long wrow = (long)blockIdx.x * 8 + (threadIdx.x >> 5);
    int  l    = threadIdx.x & 31;
    long base = wrow * Dc;

    float4 v[2];
    #pragma unroll
    for (int j = 0; j < 2; j++) {
        float4 av = *(const float4*)&a[base + j * 128 + l * 4];
        float4 rv = *(const float4*)&res[base + j * 128 + l * 4];
        v[j] = make_float4(av.x + rv.x, av.y + rv.y, av.z + rv.z, av.w + rv.w);
    }

    float s = (v[0].x + v[0].y + v[0].z + v[0].w)
            + (v[1].x + v[1].y + v[1].z + v[1].w);
    #pragma unroll
    for (int o = 16; o > 0; o >>= 1) s += __shfl_xor_sync(0xffffffffu, s, o);
    float mean = s * (1.0f / Dc);

    float q = 0.0f;
    #pragma unroll
    for (int j = 0; j < 2; j++) {
        float dx = v[j].x - mean, dy = v[j].y - mean;
        float dz = v[j].z - mean, dw = v[j].w - mean;
        q += dx*dx + dy*dy + dz*dz + dw*dw;
    }
    #pragma unroll
    for (int o = 16; o > 0; o >>= 1) q += __shfl_xor_sync(0xffffffffu, q, o);
    float rstd = rsqrtf(q * (1.0f / Dc) + LN_EPS);

    #pragma unroll
    for (int j = 0; j < 2; j++) {
        int c = j * 128 + l * 4;
        float o0 = (v[j].x - mean) * rstd * sg[c]     + bg[c];
        float o1 = (v[j].y - mean) * rstd * sg[c + 1] + bg[c + 1];
        float o2 = (v[j].z - mean) * rstd * sg[c + 2] + bg[c + 2];
        float o3 = (v[j].w - mean) * rstd * sg[c + 3] + bg[c + 3];
        *(float4*)&outF[base + c] = make_float4(o0, o1, o2, o3);
        *(__half2*)&outH[base + c]     = __floats2half2_rn(o0, o1);
        *(__half2*)&outH[base + c + 2] = __floats2half2_rn(o2, o3);
    }
}

// ---------------------------------------------------------------------------
// Warp-per-row split-K reduce (4 slabs) + bias + residual + LayerNorm.
// ---------------------------------------------------------------------------
__global__ void __launch_bounds__(256) ln4_k(
    const float* __restrict__ part, const float* __restrict__ bias,
    const float* __restrict__ res,
    const float* __restrict__ sg, const float* __restrict__ bg,
    float* __restrict__ outF, __half* __restrict__ outH)
{
    long wrow = (long)blockIdx.x * 8 + (threadIdx.x >> 5);
    int  l    = threadIdx.x & 31;
    long base = wrow * Dc;
    const long SS = (long)NROWS * Dc;

    float4 v[2];
    #pragma unroll
    for (int j = 0; j < 2; j++) {
        long i = base + j * 128 + l * 4;
        float4 p0 = *(const float4*)&part[i];
        float4 p1 = *(const float4*)&part[i + SS];
        float4 p2 = *(const float4*)&part[i + 2*SS];
        float4 p3 = *(const float4*)&part[i + 3*SS];
        float4 rv = *(const float4*)&res[i];
        int c = j * 128 + l * 4;
        v[j] = make_float4(p0.x + p1.x + p2.x + p3.x + bias[c]     + rv.x,
                           p0.y + p1.y + p2.y + p3.y + bias[c + 1] + rv.y,
                           p0.z + p1.z + p2.z + p3.z + bias[c + 2] + rv.z,
                           p0.w + p1.w + p2.w + p3.w + bias[c + 3] + rv.w);
    }

    float s = (v[0].x + v[0].y + v[0].z + v[0].w)
            + (v[1].x + v[1].y + v[1].z + v[1].w);
    #pragma unroll
    for (int o = 16; o > 0; o >>= 1) s += __shfl_xor_sync(0xffffffffu, s, o);
    float mean = s * (1.0f / Dc);

    float q = 0.0f;
    #pragma unroll
    for (int j = 0; j < 2; j++) {
        float dx = v[j].x - mean, dy = v[j].y - mean;
        float dz = v[j].z - mean, dw = v[j].w - mean;
        q += dx*dx + dy*dy + dz*dz + dw*dw;
    }
    #pragma unroll
    for (int o = 16; o > 0; o >>= 1) q += __shfl_xor_sync(0xffffffffu, q, o);
    float rstd = rsqrtf(q * (1.0f / Dc) + LN_EPS);

    #pragma unroll
    for (int j = 0; j < 2; j++) {
        int c = j * 128 + l * 4;
        float o0 = (v[j].x - mean) * rstd * sg[c]     + bg[c];
        float o1 = (v[j].y - mean) * rstd * sg[c + 1] + bg[c + 1];
        float o2 = (v[j].z - mean) * rstd * sg[c + 2] + bg[c + 2];
        float o3 = (v[j].w - mean) * rstd * sg[c + 3] + bg[c + 3];
        *(float4*)&outF[base + c] = make_float4(o0, o1, o2, o3);
        *(__half2*)&outH[base + c]     = __floats2half2_rn(o0, o1);
        *(__half2*)&outH[base + c + 2] = __floats2half2_rn(o2, o3);
    }
}

// ---------------------------------------------------------------------------
// Launch
// ---------------------------------------------------------------------------
extern "C" void kernel_launch(void* const* d_in, const int* in_sizes, int n_in,
                              void* d_out, int out_size)
{
    const float* queries = (const float*)d_in[0];
    const float* Wq   = (const float*)d_in[1];
    const float* bq   = (const float*)d_in[2];
    const float* Wk   = (const float*)d_in[3];
    const float* bk   = (const float*)d_in[4];
    const float* Wv   = (const float*)d_in[5];
    const float* bv   = (const float*)d_in[6];
    const float* Wo   = (const float*)d_in[7];
    const float* bo   = (const float*)d_in[8];
    const float* ln1s = (const float*)d_in[9];
    const float* ln1b = (const float*)d_in[10];
    const float* W1   = (const float*)d_in[11];
    const float* b1   = (const float*)d_in[12];
    const float* W2   = (const float*)d_in[13];
    const float* b2   = (const float*)d_in[14];
    const float* ln2s = (const float*)d_in[15];
    const float* ln2b = (const float*)d_in[16];

    float *x, *part, *bqkv;
    __half *xh, *qkvh, *aoh, *hh;
    __half *wqkvh, *woh, *w1h, *w2h;
    cudaGetSymbolAddress((void**)&x,     g_x);
    cudaGetSymbolAddress((void**)&part,  g_part);
    cudaGetSymbolAddress((void**)&bqkv,  g_bqkv);
    cudaGetSymbolAddress((void**)&xh,    g_xh);
    cudaGetSymbolAddress((void**)&qkvh,  g_qkvh);
    cudaGetSymbolAddress((void**)&aoh,   g_aoh);
    cudaGetSymbolAddress((void**)&hh,    g_hh);
    cudaGetSymbolAddress((void**)&wqkvh, g_wqkvh);
    cudaGetSymbolAddress((void**)&woh,   g_woh);
    cudaGetSymbolAddress((void**)&w1h,   g_w1h);
    cudaGetSymbolAddress((void**)&w2h,   g_w2h);

    const int SMH_T = 3 * (128*144 + 64*272);   // 107520
    cudaFuncSetAttribute(gemm_h<true>, cudaFuncAttributeMaxDynamicSharedMemorySize, SMH_T);
    cudaFuncSetAttribute(flash_k, cudaFuncAttributeMaxDynamicSharedMemorySize, FA_SMEM);

    const float* xin = queries;
    const float qscale = 1.0f / 16.0f;

    cvt_all_k<<<4102, 256>>>(queries, Wq, Wk, Wv, Wo, W1, W2, bq, bk, bv);

    __half* qh = qkvh;
    __half* kh = qkvh + (long)NROWS * HD;
    __half* vh = qkvh + 2L * NROWS * HD;

    for (int l = 0; l < Lc; l++) {
        const __half* wqkv = wqkvh + (long)l * 3 * Dc * HD;
        const __half* w1 = w1h + (long)l * Dc * Mc;
        const __half* w2 = w2h + (long)l * Mc * Dc;
        const __half* wo = woh + (long)l * HD * Dc;
        const float* bql3 = bqkv + (long)l * 3 * HD;
        const float* bol = bo + (long)l * Dc;
        const float* b1l = b1 + (long)l * Mc;
        const float* b2l = b2 + (long)l * Dc;
        const float* s1l = ln1s + (long)l * Dc;
        const float* o1l = ln1b + (long)l * Dc;
        const float* s2l = ln2s + (long)l * Dc;
        const float* o2l = ln2b + (long)l * Dc;

        // Fused QKV (768 CTAs, K=256)
        gemm_h<true><<<dim3(HD/128, NROWS/128, 3), 256, SMH_T>>>(
            xh, wqkv, nullptr, qkvh, bql3, Dc, Dc, HD, HD,
            0, 0, (long)Dc*HD, 0, (long)NROWS*HD, 0, (long)HD,
            1, 1.0f, 0);

        // Fused attention (replaces QK GEMM + softmax + PV GEMM)
        flash_k<<<dim3(8, 16), 256, FA_SMEM>>>(qh, kh, vh, aoh, qscale);

        // Wo split-K=4
        gemm_h<true><<<dim3(Dc/128, NROWS/128, 4), 256, SMH_T>>>(
            aoh, wo, part, nullptr, nullptr, 256, HD, Dc, Dc,
            256L, 0, 256L*Dc, 0, (long)NROWS*Dc, 0, 0,
            1, 1.0f, 0);

        ln4_k<<<NROWS/8, 256>>>(part, bol, xin, s1l, o1l, x, xh);

        // MLP1: [4096,256]x[256,1024] ReLU
        gemm_h<true><<<dim3(Mc/128, NROWS/128, 1), 256, SMH_T>>>(
            xh, w1, nullptr, hh, b1l, Dc, Dc, Mc, Mc,
            0,0,0,0,0,0,0, 1, 1.0f, 2);

        // MLP2 split-K=4
        gemm_h<true><<<dim3(Dc/128, NROWS/128, 4), 256, SMH_T>>>(
            hh, w2, part, nullptr, nullptr, 256, Mc, Dc, Dc,
            256L, 0, 256L*Dc, 0, (long)NROWS*Dc, 0, 0,
            1, 1.0f, 0);

        float* lnout = (l == Lc - 1) ? (float*)d_out : x;
        ln4_k<<<NROWS/8, 256>>>(part, b2l, x, s2l, o2l, lnout, xh);

        xin = x;
    }
}